// round 3
// baseline (speedup 1.0000x reference)
#include <cuda_runtime.h>
#include <math.h>

// Problem constants
#define NA  1024   // N atoms
#define EE  8192   // E edges
#define MM  8192   // M envelope table
#define BB  64     // B batches
#define INC 512    // IN_CH
#define HC  1024   // H_CH
#define NH  8      // heads
#define HD  128    // head dim

// ---------------- scratch (__device__ globals: sanctioned, no allocs) ----------------
__device__ float g_qp[NA * HC];
__device__ float g_kp[NA * HC];
__device__ float g_vp[NA * HC];
__device__ float g_bias[(size_t)EE * NA];           // 32 MB: bias_g[e][n]
__device__ float g_scores[(size_t)NH * EE * NA];    // 256 MB: scores[h][e][n]
__device__ float g_max[BB * NH * NA];
__device__ float g_sum[BB * NH * NA];
__device__ float g_attn[NA * HC];                   // out_nhd flattened [n][h*D+d]
__device__ float g_ln[NA * HC];
__device__ int   g_seg[BB + 1];

// ---------------- packed f32x2 helpers (sm_100+) ----------------
__device__ __forceinline__ unsigned long long pack2(float x, float y) {
    unsigned long long r;
    asm("mov.b64 %0, {%1, %2};" : "=l"(r) : "f"(x), "f"(y));
    return r;
}
__device__ __forceinline__ float2 unpack2(unsigned long long v) {
    float2 r;
    asm("mov.b64 {%0, %1}, %2;" : "=f"(r.x), "=f"(r.y) : "l"(v));
    return r;
}
__device__ __forceinline__ void fma2(unsigned long long& d, unsigned long long a,
                                     unsigned long long b) {
    asm("fma.rn.f32x2 %0, %1, %2, %0;" : "+l"(d) : "l"(a), "l"(b));
}

// ---------------- generic C[M,N] = A[M,K] @ B[N,K]^T + bias[N] ----------------
// 64x64 tile, BK=16, 256 threads, 4x4 outputs/thread (as 4x2 f32x2)
__global__ void __launch_bounds__(256) gemm_abT(
    const float* __restrict__ A, const float* __restrict__ B,
    const float* __restrict__ bias, float* __restrict__ C,
    int M, int N, int K)
{
    __shared__ float As[16][68];
    __shared__ float Bs[16][68];
    const int m0 = blockIdx.y * 64, n0 = blockIdx.x * 64;
    const int tid = threadIdx.x;
    const int tx = tid & 15, ty = tid >> 4;
    const int lr = tid >> 2, lk = (tid & 3) << 2;
    unsigned long long acc[4][2] = {};

    for (int k0 = 0; k0 < K; k0 += 16) {
        float4 a = *(const float4*)(A + (size_t)(m0 + lr) * K + k0 + lk);
        float4 b = *(const float4*)(B + (size_t)(n0 + lr) * K + k0 + lk);
        As[lk + 0][lr] = a.x; As[lk + 1][lr] = a.y; As[lk + 2][lr] = a.z; As[lk + 3][lr] = a.w;
        Bs[lk + 0][lr] = b.x; Bs[lk + 1][lr] = b.y; Bs[lk + 2][lr] = b.z; Bs[lk + 3][lr] = b.w;
        __syncthreads();
#pragma unroll
        for (int kk = 0; kk < 16; kk++) {
            float4 av = *(const float4*)&As[kk][ty * 4];
            unsigned long long b0 = *(const unsigned long long*)&Bs[kk][tx * 4];
            unsigned long long b1 = *(const unsigned long long*)&Bs[kk][tx * 4 + 2];
            unsigned long long a0 = pack2(av.x, av.x), a1 = pack2(av.y, av.y);
            unsigned long long a2 = pack2(av.z, av.z), a3 = pack2(av.w, av.w);
            fma2(acc[0][0], a0, b0); fma2(acc[0][1], a0, b1);
            fma2(acc[1][0], a1, b0); fma2(acc[1][1], a1, b1);
            fma2(acc[2][0], a2, b0); fma2(acc[2][1], a2, b1);
            fma2(acc[3][0], a3, b0); fma2(acc[3][1], a3, b1);
        }
        __syncthreads();
    }
    const int n = n0 + tx * 4;
    float4 bb = *(const float4*)(bias + n);
#pragma unroll
    for (int i = 0; i < 4; i++) {
        float2 c0 = unpack2(acc[i][0]), c1 = unpack2(acc[i][1]);
        float4 r;
        r.x = c0.x + bb.x; r.y = c0.y + bb.y; r.z = c1.x + bb.z; r.w = c1.y + bb.w;
        *(float4*)(C + (size_t)(m0 + ty * 4 + i) * N + n) = r;
    }
}

// ---------------- bias_g[e][n] = attn_bias[n][map[e]] ----------------
__global__ void bias_gather(const float* __restrict__ attn_bias,
                            const int* __restrict__ edge_map)
{
    const int e = blockIdx.y;
    const int n = blockIdx.x * 256 + threadIdx.x;
    const int m = __ldg(edge_map + e);
    g_bias[(size_t)e * NA + n] = __ldg(attn_bias + (size_t)n * MM + m);
}

// ---------------- segment boundaries (batch_index is sorted) ----------------
__global__ void seg_kernel(const int* __restrict__ batch_index)
{
    const int b = threadIdx.x;
    if (b <= BB) {
        int lo = 0, hi = EE;
        while (lo < hi) {
            int mid = (lo + hi) >> 1;
            if (batch_index[mid] < b) lo = mid + 1; else hi = mid;
        }
        g_seg[b] = lo;
    }
}

// ---------------- scores[h][e][n] = K_e . Q_n / sqrt(D) + bias_g[e][n] ----------------
__global__ void __launch_bounds__(256) score_kernel(const int* __restrict__ atom_index)
{
    __shared__ float As[16][68];   // K rows (gathered edges)
    __shared__ float Bs[16][68];   // Q rows
    __shared__ int rowA[64];
    const int h  = blockIdx.z;
    const int n0 = blockIdx.x * 64;
    const int e0 = blockIdx.y * 64;
    const int tid = threadIdx.x;
    const int tx = tid & 15, ty = tid >> 4;
    const int lr = tid >> 2, lk = (tid & 3) << 2;
    if (tid < 64) rowA[tid] = atom_index[e0 + tid];
    __syncthreads();

    unsigned long long acc[4][2] = {};
    const float* kbase = g_kp + h * HD;
    const float* qbase = g_qp + h * HD;
#pragma unroll
    for (int k0 = 0; k0 < HD; k0 += 16) {
        float4 a = *(const float4*)(kbase + (size_t)rowA[lr] * HC + k0 + lk);
        float4 b = *(const float4*)(qbase + (size_t)(n0 + lr) * HC + k0 + lk);
        As[lk + 0][lr] = a.x; As[lk + 1][lr] = a.y; As[lk + 2][lr] = a.z; As[lk + 3][lr] = a.w;
        Bs[lk + 0][lr] = b.x; Bs[lk + 1][lr] = b.y; Bs[lk + 2][lr] = b.z; Bs[lk + 3][lr] = b.w;
        __syncthreads();
#pragma unroll
        for (int kk = 0; kk < 16; kk++) {
            float4 av = *(const float4*)&As[kk][ty * 4];
            unsigned long long b0 = *(const unsigned long long*)&Bs[kk][tx * 4];
            unsigned long long b1 = *(const unsigned long long*)&Bs[kk][tx * 4 + 2];
            unsigned long long a0 = pack2(av.x, av.x), a1 = pack2(av.y, av.y);
            unsigned long long a2 = pack2(av.z, av.z), a3 = pack2(av.w, av.w);
            fma2(acc[0][0], a0, b0); fma2(acc[0][1], a0, b1);
            fma2(acc[1][0], a1, b0); fma2(acc[1][1], a1, b1);
            fma2(acc[2][0], a2, b0); fma2(acc[2][1], a2, b1);
            fma2(acc[3][0], a3, b0); fma2(acc[3][1], a3, b1);
        }
        __syncthreads();
    }
    const float scale = 0.08838834764831845f;   // 1/sqrt(128)
    const int n = n0 + tx * 4;
#pragma unroll
    for (int i = 0; i < 4; i++) {
        const int e = e0 + ty * 4 + i;
        float4 bb = *(const float4*)(g_bias + (size_t)e * NA + n);
        float2 c0 = unpack2(acc[i][0]), c1 = unpack2(acc[i][1]);
        float4 r;
        r.x = c0.x * scale + bb.x; r.y = c0.y * scale + bb.y;
        r.z = c1.x * scale + bb.z; r.w = c1.y * scale + bb.w;
        *(float4*)(g_scores + ((size_t)h * EE + e) * NA + n) = r;
    }
}

// ---------------- per-(b,h,n) online max + env-weighted exp-sum ----------------
__global__ void __launch_bounds__(256) reduce_kernel(
    const float* __restrict__ envelope, const int* __restrict__ edge_map)
{
    const int b = blockIdx.z, h = blockIdx.y;
    const int n = blockIdx.x * 256 + threadIdx.x;
    const int s0 = g_seg[b], s1 = g_seg[b + 1];
    __shared__ float s_env[128];
    const float* base = g_scores + (size_t)h * EE * NA + n;
    float m = -INFINITY, s = 0.f;
    for (int c = s0; c < s1; c += 128) {
        const int cnt = min(128, s1 - c);
        __syncthreads();
        if (threadIdx.x < 128 && threadIdx.x < cnt)
            s_env[threadIdx.x] = envelope[edge_map[c + threadIdx.x]];
        __syncthreads();
        for (int i = 0; i < cnt; i++) {
            float x = base[(size_t)(c + i) * NA];
            float env = s_env[i];
            if (x > m) { s = s * expf(m - x) + env; m = x; }
            else       { s += env * expf(x - m); }
        }
    }
    const size_t o = ((size_t)b * NH + h) * NA + n;
    g_max[o] = m;
    g_sum[o] = s;
}

// ---------------- out[n][h][d] = sum_e w[e,h,n] * v[e,h,d] ----------------
// grid (N/32, H); each CTA owns a 32-n tile for one head and streams all edges.
__global__ void __launch_bounds__(256) out_kernel(
    const int* __restrict__ atom_index, const int* __restrict__ batch_index,
    const int* __restrict__ edge_map, const float* __restrict__ envelope)
{
    __shared__ float s_w[32][36];     // w[e][n] (padded rows, 16B-aligned stride)
    __shared__ float s_v[32][128];    // v[e][d]
    __shared__ float s_env2[32];
    __shared__ int s_a[32];
    __shared__ int s_b[32];
    const int h  = blockIdx.y;
    const int n0 = blockIdx.x * 32;
    const int tid = threadIdx.x;
    const int nloc = (tid & 15) * 2;   // 2 n per thread
    const int dloc = (tid >> 4) * 8;   // 8 d per thread
    const int wr = tid >> 3, wc = (tid & 7) * 4;  // score-tile load coords
    unsigned long long acc[2][4] = {};

    for (int e0 = 0; e0 < EE; e0 += 32) {
        __syncthreads();
        if (tid < 32) {
            s_a[tid] = atom_index[e0 + tid];
            s_b[tid] = batch_index[e0 + tid];
            float env = envelope[edge_map[e0 + tid]];
            s_env2[tid] = env * env;
        }
        __syncthreads();
        // gathered V tile: 32 rows x 128
#pragma unroll
        for (int kk = 0; kk < 4; kk++) {
            int idx = tid + kk * 256;
            int r = idx >> 5, c = (idx & 31) * 4;
            *(float4*)&s_v[r][c] =
                *(const float4*)(g_vp + (size_t)s_a[r] * HC + h * HD + c);
        }
        // scores -> w
        {
            float4 sc = *(const float4*)(g_scores + ((size_t)h * EE + e0 + wr) * NA + n0 + wc);
            const size_t mb = ((size_t)s_b[wr] * NH + h) * NA + n0 + wc;
            float4 m4 = *(const float4*)(g_max + mb);
            float4 q4 = *(const float4*)(g_sum + mb);
            float env2 = s_env2[wr];
            float4 w;
            w.x = expf(sc.x - m4.x) * env2 / (q4.x + 1e-16f);
            w.y = expf(sc.y - m4.y) * env2 / (q4.y + 1e-16f);
            w.z = expf(sc.z - m4.z) * env2 / (q4.z + 1e-16f);
            w.w = expf(sc.w - m4.w) * env2 / (q4.w + 1e-16f);
            *(float4*)&s_w[wr][wc] = w;
        }
        __syncthreads();
#pragma unroll 8
        for (int e = 0; e < 32; e++) {
            float w0f = s_w[e][nloc];
            float w1f = s_w[e][nloc + 1];
            unsigned long long w0 = pack2(w0f, w0f);
            unsigned long long w1 = pack2(w1f, w1f);
            const unsigned long long* vr = (const unsigned long long*)&s_v[e][dloc];
#pragma unroll
            for (int j = 0; j < 4; j++) {
                unsigned long long vv = vr[j];
                fma2(acc[0][j], w0, vv);
                fma2(acc[1][j], w1, vv);
            }
        }
    }
#pragma unroll
    for (int i = 0; i < 2; i++) {
        float2 p0 = unpack2(acc[i][0]);
        float2 p1 = unpack2(acc[i][1]);
        float2 p2 = unpack2(acc[i][2]);
        float2 p3 = unpack2(acc[i][3]);
        float* o = g_attn + (size_t)(n0 + nloc + i) * HC + h * HD + dloc;
        float4 r0; r0.x = p0.x; r0.y = p0.y; r0.z = p1.x; r0.w = p1.y;
        float4 r1; r1.x = p2.x; r1.y = p2.y; r1.z = p3.x; r1.w = p3.y;
        *(float4*)o = r0;
        *(float4*)(o + 4) = r1;
    }
}

// ---------------- LayerNorm over H_CH per row ----------------
__global__ void __launch_bounds__(256) ln_kernel(
    const float* __restrict__ ln_g, const float* __restrict__ ln_b)
{
    const int n = blockIdx.x;
    const int tid = threadIdx.x;
    const float* x = g_attn + (size_t)n * HC;
    float s = 0.f, s2 = 0.f;
    for (int i = tid; i < HC; i += 256) {
        float v = x[i];
        s += v; s2 += v * v;
    }
#pragma unroll
    for (int o = 16; o > 0; o >>= 1) {
        s  += __shfl_xor_sync(0xffffffffu, s, o);
        s2 += __shfl_xor_sync(0xffffffffu, s2, o);
    }
    __shared__ float ws[8], ws2[8], stats[2];
    if ((tid & 31) == 0) { ws[tid >> 5] = s; ws2[tid >> 5] = s2; }
    __syncthreads();
    if (tid == 0) {
        float a = 0.f, b = 0.f;
#pragma unroll
        for (int i = 0; i < 8; i++) { a += ws[i]; b += ws2[i]; }
        float mean = a * (1.f / HC);
        float var  = b * (1.f / HC) - mean * mean;
        stats[0] = mean;
        stats[1] = rsqrtf(var + 1e-7f);
    }
    __syncthreads();
    const float mean = stats[0], inv = stats[1];
    for (int i = tid; i < HC; i += 256) {
        g_ln[(size_t)n * HC + i] = (x[i] - mean) * inv * ln_g[i] + ln_b[i];
    }
}

// ---------------- launch ----------------
extern "C" void kernel_launch(void* const* d_in, const int* in_sizes, int n_in,
                              void* d_out, int out_size)
{
    const float* q         = (const float*)d_in[0];
    const float* k         = (const float*)d_in[1];
    const float* v         = (const float*)d_in[2];
    const float* envelope  = (const float*)d_in[3];
    const float* attn_bias = (const float*)d_in[4];
    const float* Wq        = (const float*)d_in[5];
    const float* bq        = (const float*)d_in[6];
    const float* Wk        = (const float*)d_in[7];
    const float* bk        = (const float*)d_in[8];
    const float* Wv        = (const float*)d_in[9];
    const float* bv        = (const float*)d_in[10];
    const float* ln_g      = (const float*)d_in[11];
    const float* ln_b      = (const float*)d_in[12];
    const float* Wo        = (const float*)d_in[13];
    const float* bo        = (const float*)d_in[14];
    const int* atom_index  = (const int*)d_in[15];
    const int* batch_index = (const int*)d_in[16];
    const int* edge_map    = (const int*)d_in[17];
    float* out = (float*)d_out;

    float *qp, *kp, *vp, *lnp;
    cudaGetSymbolAddress((void**)&qp, g_qp);
    cudaGetSymbolAddress((void**)&kp, g_kp);
    cudaGetSymbolAddress((void**)&vp, g_vp);
    cudaGetSymbolAddress((void**)&lnp, g_ln);

    // projections: [1024,512] @ [1024,512]^T -> [1024,1024]
    gemm_abT<<<dim3(HC / 64, NA / 64), 256>>>(q, Wq, bq, qp, NA, HC, INC);
    gemm_abT<<<dim3(HC / 64, NA / 64), 256>>>(k, Wk, bk, kp, NA, HC, INC);
    gemm_abT<<<dim3(HC / 64, NA / 64), 256>>>(v, Wv, bv, vp, NA, HC, INC);

    bias_gather<<<dim3(NA / 256, EE), 256>>>(attn_bias, edge_map);
    seg_kernel<<<1, 128>>>(batch_index);

    score_kernel<<<dim3(NA / 64, EE / 64, NH), 256>>>(atom_index);
    reduce_kernel<<<dim3(NA / 256, NH, BB), 256>>>(envelope, edge_map);
    out_kernel<<<dim3(NA / 32, NH), 256>>>(atom_index, batch_index, edge_map, envelope);

    ln_kernel<<<NA, 256>>>(ln_g, ln_b);

    // final: [1024,1024] @ [512,1024]^T -> [1024,512]
    gemm_abT<<<dim3(INC / 64, NA / 64), 256>>>(lnp, Wo, bo, out, NA, INC, HC);
}

// round 4
// speedup vs baseline: 1.0044x; 1.0044x over previous
#include <cuda_runtime.h>
#include <math.h>

// Problem constants
#define NA  1024   // N atoms
#define EE  8192   // E edges
#define MM  8192   // M envelope table
#define BB  64     // B batches
#define INC 512    // IN_CH
#define HC  1024   // H_CH
#define NH  8      // heads
#define HD  128    // head dim

// ---------------- scratch (__device__ globals: sanctioned, no allocs) ----------------
__device__ float g_qp[NA * HC];
__device__ float g_kp[NA * HC];
__device__ float g_vp[NA * HC];
__device__ float g_bias[(size_t)EE * NA];           // 32 MB: bias_g[e][n]
__device__ float g_scores[(size_t)NH * EE * NA];    // 256 MB: scores[h][e][n]
__device__ float g_max[BB * NH * NA];
__device__ float g_sum[BB * NH * NA];
__device__ float g_attn[NA * HC];                   // out_nhd flattened [n][h*D+d]
__device__ float g_ln[NA * HC];
__device__ int   g_seg[BB + 1];

// ---------------- packed f32x2 helpers (sm_100+) ----------------
__device__ __forceinline__ unsigned long long pack2(float x, float y) {
    unsigned long long r;
    asm("mov.b64 %0, {%1, %2};" : "=l"(r) : "f"(x), "f"(y));
    return r;
}
__device__ __forceinline__ float2 unpack2(unsigned long long v) {
    float2 r;
    asm("mov.b64 {%0, %1}, %2;" : "=f"(r.x), "=f"(r.y) : "l"(v));
    return r;
}
__device__ __forceinline__ void fma2(unsigned long long& d, unsigned long long a,
                                     unsigned long long b) {
    asm("fma.rn.f32x2 %0, %1, %2, %0;" : "+l"(d) : "l"(a), "l"(b));
}

// ---------------- generic C[M,N] = A[M,K] @ B[N,K]^T + bias[N] ----------------
// 64x64 tile, BK=16, 256 threads, 4x4 outputs/thread (as 4x2 f32x2)
__global__ void __launch_bounds__(256) gemm_abT(
    const float* __restrict__ A, const float* __restrict__ B,
    const float* __restrict__ bias, float* __restrict__ C,
    int M, int N, int K)
{
    __shared__ float As[16][68];
    __shared__ float Bs[16][68];
    const int m0 = blockIdx.y * 64, n0 = blockIdx.x * 64;
    const int tid = threadIdx.x;
    const int tx = tid & 15, ty = tid >> 4;
    const int lr = tid >> 2, lk = (tid & 3) << 2;
    unsigned long long acc[4][2] = {};

    for (int k0 = 0; k0 < K; k0 += 16) {
        float4 a = *(const float4*)(A + (size_t)(m0 + lr) * K + k0 + lk);
        float4 b = *(const float4*)(B + (size_t)(n0 + lr) * K + k0 + lk);
        As[lk + 0][lr] = a.x; As[lk + 1][lr] = a.y; As[lk + 2][lr] = a.z; As[lk + 3][lr] = a.w;
        Bs[lk + 0][lr] = b.x; Bs[lk + 1][lr] = b.y; Bs[lk + 2][lr] = b.z; Bs[lk + 3][lr] = b.w;
        __syncthreads();
#pragma unroll
        for (int kk = 0; kk < 16; kk++) {
            float4 av = *(const float4*)&As[kk][ty * 4];
            unsigned long long b0 = *(const unsigned long long*)&Bs[kk][tx * 4];
            unsigned long long b1 = *(const unsigned long long*)&Bs[kk][tx * 4 + 2];
            unsigned long long a0 = pack2(av.x, av.x), a1 = pack2(av.y, av.y);
            unsigned long long a2 = pack2(av.z, av.z), a3 = pack2(av.w, av.w);
            fma2(acc[0][0], a0, b0); fma2(acc[0][1], a0, b1);
            fma2(acc[1][0], a1, b0); fma2(acc[1][1], a1, b1);
            fma2(acc[2][0], a2, b0); fma2(acc[2][1], a2, b1);
            fma2(acc[3][0], a3, b0); fma2(acc[3][1], a3, b1);
        }
        __syncthreads();
    }
    const int n = n0 + tx * 4;
    float4 bb = *(const float4*)(bias + n);
#pragma unroll
    for (int i = 0; i < 4; i++) {
        float2 c0 = unpack2(acc[i][0]), c1 = unpack2(acc[i][1]);
        float4 r;
        r.x = c0.x + bb.x; r.y = c0.y + bb.y; r.z = c1.x + bb.z; r.w = c1.y + bb.w;
        *(float4*)(C + (size_t)(m0 + ty * 4 + i) * N + n) = r;
    }
}

// ---------------- bias_g[e][n] = attn_bias[n][map[e]] ----------------
__global__ void bias_gather(const float* __restrict__ attn_bias,
                            const int* __restrict__ edge_map)
{
    const int e = blockIdx.y;
    const int n = blockIdx.x * 256 + threadIdx.x;
    const int m = __ldg(edge_map + e);
    g_bias[(size_t)e * NA + n] = __ldg(attn_bias + (size_t)n * MM + m);
}

// ---------------- segment boundaries (batch_index is sorted) ----------------
__global__ void seg_kernel(const int* __restrict__ batch_index)
{
    const int b = threadIdx.x;
    if (b <= BB) {
        int lo = 0, hi = EE;
        while (lo < hi) {
            int mid = (lo + hi) >> 1;
            if (batch_index[mid] < b) lo = mid + 1; else hi = mid;
        }
        g_seg[b] = lo;
    }
}

// ---------------- scores[h][e][n] = K_e . Q_n / sqrt(D) + bias_g[e][n] ----------------
__global__ void __launch_bounds__(256) score_kernel(const int* __restrict__ atom_index)
{
    __shared__ float As[16][68];   // K rows (gathered edges)
    __shared__ float Bs[16][68];   // Q rows
    __shared__ int rowA[64];
    const int h  = blockIdx.z;
    const int n0 = blockIdx.x * 64;
    const int e0 = blockIdx.y * 64;
    const int tid = threadIdx.x;
    const int tx = tid & 15, ty = tid >> 4;
    const int lr = tid >> 2, lk = (tid & 3) << 2;
    if (tid < 64) rowA[tid] = atom_index[e0 + tid];
    __syncthreads();

    unsigned long long acc[4][2] = {};
    const float* kbase = g_kp + h * HD;
    const float* qbase = g_qp + h * HD;
#pragma unroll
    for (int k0 = 0; k0 < HD; k0 += 16) {
        float4 a = *(const float4*)(kbase + (size_t)rowA[lr] * HC + k0 + lk);
        float4 b = *(const float4*)(qbase + (size_t)(n0 + lr) * HC + k0 + lk);
        As[lk + 0][lr] = a.x; As[lk + 1][lr] = a.y; As[lk + 2][lr] = a.z; As[lk + 3][lr] = a.w;
        Bs[lk + 0][lr] = b.x; Bs[lk + 1][lr] = b.y; Bs[lk + 2][lr] = b.z; Bs[lk + 3][lr] = b.w;
        __syncthreads();
#pragma unroll
        for (int kk = 0; kk < 16; kk++) {
            float4 av = *(const float4*)&As[kk][ty * 4];
            unsigned long long b0 = *(const unsigned long long*)&Bs[kk][tx * 4];
            unsigned long long b1 = *(const unsigned long long*)&Bs[kk][tx * 4 + 2];
            unsigned long long a0 = pack2(av.x, av.x), a1 = pack2(av.y, av.y);
            unsigned long long a2 = pack2(av.z, av.z), a3 = pack2(av.w, av.w);
            fma2(acc[0][0], a0, b0); fma2(acc[0][1], a0, b1);
            fma2(acc[1][0], a1, b0); fma2(acc[1][1], a1, b1);
            fma2(acc[2][0], a2, b0); fma2(acc[2][1], a2, b1);
            fma2(acc[3][0], a3, b0); fma2(acc[3][1], a3, b1);
        }
        __syncthreads();
    }
    const float scale = 0.08838834764831845f;   // 1/sqrt(128)
    const int n = n0 + tx * 4;
#pragma unroll
    for (int i = 0; i < 4; i++) {
        const int e = e0 + ty * 4 + i;
        float4 bb = *(const float4*)(g_bias + (size_t)e * NA + n);
        float2 c0 = unpack2(acc[i][0]), c1 = unpack2(acc[i][1]);
        float4 r;
        r.x = c0.x * scale + bb.x; r.y = c0.y * scale + bb.y;
        r.z = c1.x * scale + bb.z; r.w = c1.y * scale + bb.w;
        *(float4*)(g_scores + ((size_t)h * EE + e) * NA + n) = r;
    }
}

// ---------------- per-(b,h,n) online max + env-weighted exp-sum ----------------
__global__ void __launch_bounds__(256) reduce_kernel(
    const float* __restrict__ envelope, const int* __restrict__ edge_map)
{
    const int b = blockIdx.z, h = blockIdx.y;
    const int n = blockIdx.x * 256 + threadIdx.x;
    const int s0 = g_seg[b], s1 = g_seg[b + 1];
    __shared__ float s_env[128];
    const float* base = g_scores + (size_t)h * EE * NA + n;
    float m = -INFINITY, s = 0.f;
    for (int c = s0; c < s1; c += 128) {
        const int cnt = min(128, s1 - c);
        __syncthreads();
        if (threadIdx.x < 128 && threadIdx.x < cnt)
            s_env[threadIdx.x] = envelope[edge_map[c + threadIdx.x]];
        __syncthreads();
        for (int i = 0; i < cnt; i++) {
            float x = base[(size_t)(c + i) * NA];
            float env = s_env[i];
            if (x > m) { s = s * expf(m - x) + env; m = x; }
            else       { s += env * expf(x - m); }
        }
    }
    const size_t o = ((size_t)b * NH + h) * NA + n;
    g_max[o] = m;
    g_sum[o] = s;
}

// ---------------- out[n][h][d] = sum_e w[e,h,n] * v[e,h,d] ----------------
// grid (N/32, H); each CTA owns a 32-n tile for one head and streams all edges.
__global__ void __launch_bounds__(256) out_kernel(
    const int* __restrict__ atom_index, const int* __restrict__ batch_index,
    const int* __restrict__ edge_map, const float* __restrict__ envelope)
{
    __shared__ float s_w[32][36];     // w[e][n] (padded rows, 16B-aligned stride)
    __shared__ float s_v[32][128];    // v[e][d]
    __shared__ float s_env2[32];
    __shared__ int s_a[32];
    __shared__ int s_b[32];
    const int h  = blockIdx.y;
    const int n0 = blockIdx.x * 32;
    const int tid = threadIdx.x;
    const int nloc = (tid & 15) * 2;   // 2 n per thread
    const int dloc = (tid >> 4) * 8;   // 8 d per thread
    const int wr = tid >> 3, wc = (tid & 7) * 4;  // score-tile load coords
    unsigned long long acc[2][4] = {};

    for (int e0 = 0; e0 < EE; e0 += 32) {
        __syncthreads();
        if (tid < 32) {
            s_a[tid] = atom_index[e0 + tid];
            s_b[tid] = batch_index[e0 + tid];
            float env = envelope[edge_map[e0 + tid]];
            s_env2[tid] = env * env;
        }
        __syncthreads();
        // gathered V tile: 32 rows x 128
#pragma unroll
        for (int kk = 0; kk < 4; kk++) {
            int idx = tid + kk * 256;
            int r = idx >> 5, c = (idx & 31) * 4;
            *(float4*)&s_v[r][c] =
                *(const float4*)(g_vp + (size_t)s_a[r] * HC + h * HD + c);
        }
        // scores -> w
        {
            float4 sc = *(const float4*)(g_scores + ((size_t)h * EE + e0 + wr) * NA + n0 + wc);
            const size_t mb = ((size_t)s_b[wr] * NH + h) * NA + n0 + wc;
            float4 m4 = *(const float4*)(g_max + mb);
            float4 q4 = *(const float4*)(g_sum + mb);
            float env2 = s_env2[wr];
            float4 w;
            w.x = expf(sc.x - m4.x) * env2 / (q4.x + 1e-16f);
            w.y = expf(sc.y - m4.y) * env2 / (q4.y + 1e-16f);
            w.z = expf(sc.z - m4.z) * env2 / (q4.z + 1e-16f);
            w.w = expf(sc.w - m4.w) * env2 / (q4.w + 1e-16f);
            *(float4*)&s_w[wr][wc] = w;
        }
        __syncthreads();
#pragma unroll 8
        for (int e = 0; e < 32; e++) {
            float w0f = s_w[e][nloc];
            float w1f = s_w[e][nloc + 1];
            unsigned long long w0 = pack2(w0f, w0f);
            unsigned long long w1 = pack2(w1f, w1f);
            const unsigned long long* vr = (const unsigned long long*)&s_v[e][dloc];
#pragma unroll
            for (int j = 0; j < 4; j++) {
                unsigned long long vv = vr[j];
                fma2(acc[0][j], w0, vv);
                fma2(acc[1][j], w1, vv);
            }
        }
    }
#pragma unroll
    for (int i = 0; i < 2; i++) {
        float2 p0 = unpack2(acc[i][0]);
        float2 p1 = unpack2(acc[i][1]);
        float2 p2 = unpack2(acc[i][2]);
        float2 p3 = unpack2(acc[i][3]);
        float* o = g_attn + (size_t)(n0 + nloc + i) * HC + h * HD + dloc;
        float4 r0; r0.x = p0.x; r0.y = p0.y; r0.z = p1.x; r0.w = p1.y;
        float4 r1; r1.x = p2.x; r1.y = p2.y; r1.z = p3.x; r1.w = p3.y;
        *(float4*)o = r0;
        *(float4*)(o + 4) = r1;
    }
}

// ---------------- LayerNorm over H_CH per row ----------------
__global__ void __launch_bounds__(256) ln_kernel(
    const float* __restrict__ ln_g, const float* __restrict__ ln_b)
{
    const int n = blockIdx.x;
    const int tid = threadIdx.x;
    const float* x = g_attn + (size_t)n * HC;
    float s = 0.f, s2 = 0.f;
    for (int i = tid; i < HC; i += 256) {
        float v = x[i];
        s += v; s2 += v * v;
    }
#pragma unroll
    for (int o = 16; o > 0; o >>= 1) {
        s  += __shfl_xor_sync(0xffffffffu, s, o);
        s2 += __shfl_xor_sync(0xffffffffu, s2, o);
    }
    __shared__ float ws[8], ws2[8], stats[2];
    if ((tid & 31) == 0) { ws[tid >> 5] = s; ws2[tid >> 5] = s2; }
    __syncthreads();
    if (tid == 0) {
        float a = 0.f, b = 0.f;
#pragma unroll
        for (int i = 0; i < 8; i++) { a += ws[i]; b += ws2[i]; }
        float mean = a * (1.f / HC);
        float var  = b * (1.f / HC) - mean * mean;
        stats[0] = mean;
        stats[1] = rsqrtf(var + 1e-7f);
    }
    __syncthreads();
    const float mean = stats[0], inv = stats[1];
    for (int i = tid; i < HC; i += 256) {
        g_ln[(size_t)n * HC + i] = (x[i] - mean) * inv * ln_g[i] + ln_b[i];
    }
}

// ---------------- launch ----------------
extern "C" void kernel_launch(void* const* d_in, const int* in_sizes, int n_in,
                              void* d_out, int out_size)
{
    const float* q         = (const float*)d_in[0];
    const float* k         = (const float*)d_in[1];
    const float* v         = (const float*)d_in[2];
    const float* envelope  = (const float*)d_in[3];
    const float* attn_bias = (const float*)d_in[4];
    const float* Wq        = (const float*)d_in[5];
    const float* bq        = (const float*)d_in[6];
    const float* Wk        = (const float*)d_in[7];
    const float* bk        = (const float*)d_in[8];
    const float* Wv        = (const float*)d_in[9];
    const float* bv        = (const float*)d_in[10];
    const float* ln_g      = (const float*)d_in[11];
    const float* ln_b      = (const float*)d_in[12];
    const float* Wo        = (const float*)d_in[13];
    const float* bo        = (const float*)d_in[14];
    const int* atom_index  = (const int*)d_in[15];
    const int* batch_index = (const int*)d_in[16];
    const int* edge_map    = (const int*)d_in[17];
    float* out = (float*)d_out;

    float *qp, *kp, *vp, *lnp;
    cudaGetSymbolAddress((void**)&qp, g_qp);
    cudaGetSymbolAddress((void**)&kp, g_kp);
    cudaGetSymbolAddress((void**)&vp, g_vp);
    cudaGetSymbolAddress((void**)&lnp, g_ln);

    // projections: [1024,512] @ [1024,512]^T -> [1024,1024]
    gemm_abT<<<dim3(HC / 64, NA / 64), 256>>>(q, Wq, bq, qp, NA, HC, INC);
    gemm_abT<<<dim3(HC / 64, NA / 64), 256>>>(k, Wk, bk, kp, NA, HC, INC);
    gemm_abT<<<dim3(HC / 64, NA / 64), 256>>>(v, Wv, bv, vp, NA, HC, INC);

    bias_gather<<<dim3(NA / 256, EE), 256>>>(attn_bias, edge_map);
    seg_kernel<<<1, 128>>>(batch_index);

    score_kernel<<<dim3(NA / 64, EE / 64, NH), 256>>>(atom_index);
    reduce_kernel<<<dim3(NA / 256, NH, BB), 256>>>(envelope, edge_map);
    out_kernel<<<dim3(NA / 32, NH), 256>>>(atom_index, batch_index, edge_map, envelope);

    ln_kernel<<<NA, 256>>>(ln_g, ln_b);

    // final: [1024,1024] @ [512,1024]^T -> [1024,512]
    gemm_abT<<<dim3(INC / 64, NA / 64), 256>>>(lnp, Wo, bo, out, NA, INC, HC);
}

// round 5
// speedup vs baseline: 3.5744x; 3.5588x over previous
#include <cuda_runtime.h>
#include <math.h>

// Problem constants
#define NA  1024   // N atoms
#define EE  8192   // E edges
#define MM  8192   // M envelope table
#define BB  64     // B batches
#define INC 512    // IN_CH
#define HC  1024   // H_CH
#define NH  8      // heads
#define HD  128    // head dim

// ---------------- scratch ----------------
__device__ float g_qp[NA * HC];
__device__ float g_kp[NA * HC];
__device__ float g_vp[NA * HC];
__device__ float g_biasT[(size_t)MM * NA];          // 32 MB: biasT[m][n] = attn_bias[n][m]
__device__ float g_S0[(size_t)NH * NA * NA];        // 32 MB: S0[h][a][n]
__device__ float g_W2[(size_t)NH * NA * NA];        // 32 MB: W2[h][a][n]
__device__ float g_C[(size_t)BB * NH * NA];         // 2 MB:  C[b][h][n] = exp(-m)/(sum+eps)
__device__ float g_attn[NA * HC];
__device__ float g_ln[NA * HC];
__device__ int   g_seg[BB + 1];
__device__ int   g_deg[NA];
__device__ int   g_off[NA + 1];
__device__ int   g_csr[EE];                         // edge ids grouped by atom, e-order

// ---------------- packed f32x2 helpers (sm_100+) ----------------
__device__ __forceinline__ unsigned long long pack2(float x, float y) {
    unsigned long long r;
    asm("mov.b64 %0, {%1, %2};" : "=l"(r) : "f"(x), "f"(y));
    return r;
}
__device__ __forceinline__ float2 unpack2(unsigned long long v) {
    float2 r;
    asm("mov.b64 {%0, %1}, %2;" : "=f"(r.x), "=f"(r.y) : "l"(v));
    return r;
}
__device__ __forceinline__ void fma2(unsigned long long& d, unsigned long long a,
                                     unsigned long long b) {
    asm("fma.rn.f32x2 %0, %1, %2, %0;" : "+l"(d) : "l"(a), "l"(b));
}

// ---------------- generic C[M,N] = A[M,K] @ B[N,K]^T + bias[N] ----------------
__global__ void __launch_bounds__(256) gemm_abT(
    const float* __restrict__ A, const float* __restrict__ B,
    const float* __restrict__ bias, float* __restrict__ C,
    int M, int N, int K)
{
    __shared__ float As[16][68];
    __shared__ float Bs[16][68];
    const int m0 = blockIdx.y * 64, n0 = blockIdx.x * 64;
    const int tid = threadIdx.x;
    const int tx = tid & 15, ty = tid >> 4;
    const int lr = tid >> 2, lk = (tid & 3) << 2;
    unsigned long long acc[4][2] = {};

    for (int k0 = 0; k0 < K; k0 += 16) {
        float4 a = *(const float4*)(A + (size_t)(m0 + lr) * K + k0 + lk);
        float4 b = *(const float4*)(B + (size_t)(n0 + lr) * K + k0 + lk);
        As[lk + 0][lr] = a.x; As[lk + 1][lr] = a.y; As[lk + 2][lr] = a.z; As[lk + 3][lr] = a.w;
        Bs[lk + 0][lr] = b.x; Bs[lk + 1][lr] = b.y; Bs[lk + 2][lr] = b.z; Bs[lk + 3][lr] = b.w;
        __syncthreads();
#pragma unroll
        for (int kk = 0; kk < 16; kk++) {
            float4 av = *(const float4*)&As[kk][ty * 4];
            unsigned long long b0 = *(const unsigned long long*)&Bs[kk][tx * 4];
            unsigned long long b1 = *(const unsigned long long*)&Bs[kk][tx * 4 + 2];
            unsigned long long a0 = pack2(av.x, av.x), a1 = pack2(av.y, av.y);
            unsigned long long a2 = pack2(av.z, av.z), a3 = pack2(av.w, av.w);
            fma2(acc[0][0], a0, b0); fma2(acc[0][1], a0, b1);
            fma2(acc[1][0], a1, b0); fma2(acc[1][1], a1, b1);
            fma2(acc[2][0], a2, b0); fma2(acc[2][1], a2, b1);
            fma2(acc[3][0], a3, b0); fma2(acc[3][1], a3, b1);
        }
        __syncthreads();
    }
    const int n = n0 + tx * 4;
    float4 bb = *(const float4*)(bias + n);
#pragma unroll
    for (int i = 0; i < 4; i++) {
        float2 c0 = unpack2(acc[i][0]), c1 = unpack2(acc[i][1]);
        float4 r;
        r.x = c0.x + bb.x; r.y = c0.y + bb.y; r.z = c1.x + bb.z; r.w = c1.y + bb.w;
        *(float4*)(C + (size_t)(m0 + ty * 4 + i) * N + n) = r;
    }
}

// ---------------- biasT[m][n] = attn_bias[n][m] (tiled transpose) ----------------
__global__ void __launch_bounds__(256) transpose_bias(const float* __restrict__ src)
{
    __shared__ float tile[32][33];
    const int m0 = blockIdx.x * 32, n0 = blockIdx.y * 32;
    const int tx = threadIdx.x, ty = threadIdx.y;
    const int m = m0 + tx;
#pragma unroll
    for (int i = ty; i < 32; i += 8)
        tile[i][tx] = src[(size_t)(n0 + i) * MM + m];
    __syncthreads();
    const int n = n0 + tx;
#pragma unroll
    for (int i = ty; i < 32; i += 8)
        g_biasT[(size_t)(m0 + i) * NA + n] = tile[tx][i];
}

// ---------------- segment boundaries (batch_index is sorted) ----------------
__global__ void seg_kernel(const int* __restrict__ batch_index)
{
    const int b = threadIdx.x;
    if (b <= BB) {
        int lo = 0, hi = EE;
        while (lo < hi) {
            int mid = (lo + hi) >> 1;
            if (batch_index[mid] < b) lo = mid + 1; else hi = mid;
        }
        g_seg[b] = lo;
    }
}

// ---------------- CSR build: group edges by atom (deterministic, e-order) ----------------
// warp per atom, ballot-based counting
__global__ void __launch_bounds__(256) deg_kernel(const int* __restrict__ atom_index)
{
    const int w = (blockIdx.x * 256 + threadIdx.x) >> 5;   // atom id
    const int lane = threadIdx.x & 31;
    int cnt = 0;
    for (int base = 0; base < EE; base += 32) {
        int a = atom_index[base + lane];
        unsigned mask = __ballot_sync(0xffffffffu, a == w);
        cnt += __popc(mask);
    }
    if (lane == 0) g_deg[w] = cnt;
}

__global__ void __launch_bounds__(1024) scan_kernel()
{
    __shared__ int buf[1024];
    const int tid = threadIdx.x;
    int d = g_deg[tid];
    buf[tid] = d;
    __syncthreads();
    for (int s = 1; s < 1024; s <<= 1) {
        int v = (tid >= s) ? buf[tid - s] : 0;
        __syncthreads();
        buf[tid] += v;
        __syncthreads();
    }
    g_off[tid + 1] = buf[tid];    // inclusive -> off[a+1]
    if (tid == 0) g_off[0] = 0;
}

__global__ void __launch_bounds__(256) fill_kernel(const int* __restrict__ atom_index)
{
    const int w = (blockIdx.x * 256 + threadIdx.x) >> 5;
    const int lane = threadIdx.x & 31;
    int o = g_off[w];
    for (int base = 0; base < EE; base += 32) {
        int a = atom_index[base + lane];
        bool match = (a == w);
        unsigned mask = __ballot_sync(0xffffffffu, match);
        int rank = __popc(mask & ((1u << lane) - 1));
        if (match) g_csr[o + rank] = base + lane;
        o += __popc(mask);
    }
}

// ---------------- S0[h][a][n] = dot(k_a, q_n)/sqrt(D) (dense, per head) ----------------
__global__ void __launch_bounds__(256) s0_kernel()
{
    __shared__ float As[16][68];   // K rows (atoms)
    __shared__ float Bs[16][68];   // Q rows
    const int h  = blockIdx.z;
    const int n0 = blockIdx.x * 64;
    const int a0 = blockIdx.y * 64;
    const int tid = threadIdx.x;
    const int tx = tid & 15, ty = tid >> 4;
    const int lr = tid >> 2, lk = (tid & 3) << 2;

    unsigned long long acc[4][2] = {};
    const float* kbase = g_kp + h * HD;
    const float* qbase = g_qp + h * HD;
#pragma unroll
    for (int k0 = 0; k0 < HD; k0 += 16) {
        float4 a = *(const float4*)(kbase + (size_t)(a0 + lr) * HC + k0 + lk);
        float4 b = *(const float4*)(qbase + (size_t)(n0 + lr) * HC + k0 + lk);
        As[lk + 0][lr] = a.x; As[lk + 1][lr] = a.y; As[lk + 2][lr] = a.z; As[lk + 3][lr] = a.w;
        Bs[lk + 0][lr] = b.x; Bs[lk + 1][lr] = b.y; Bs[lk + 2][lr] = b.z; Bs[lk + 3][lr] = b.w;
        __syncthreads();
#pragma unroll
        for (int kk = 0; kk < 16; kk++) {
            float4 av = *(const float4*)&As[kk][ty * 4];
            unsigned long long b0 = *(const unsigned long long*)&Bs[kk][tx * 4];
            unsigned long long b1 = *(const unsigned long long*)&Bs[kk][tx * 4 + 2];
            unsigned long long a0p = pack2(av.x, av.x), a1p = pack2(av.y, av.y);
            unsigned long long a2p = pack2(av.z, av.z), a3p = pack2(av.w, av.w);
            fma2(acc[0][0], a0p, b0); fma2(acc[0][1], a0p, b1);
            fma2(acc[1][0], a1p, b0); fma2(acc[1][1], a1p, b1);
            fma2(acc[2][0], a2p, b0); fma2(acc[2][1], a2p, b1);
            fma2(acc[3][0], a3p, b0); fma2(acc[3][1], a3p, b1);
        }
        __syncthreads();
    }
    const float scale = 0.08838834764831845f;   // 1/sqrt(128)
    const int n = n0 + tx * 4;
#pragma unroll
    for (int i = 0; i < 4; i++) {
        const int a = a0 + ty * 4 + i;
        float2 c0 = unpack2(acc[i][0]), c1 = unpack2(acc[i][1]);
        float4 r;
        r.x = c0.x * scale; r.y = c0.y * scale;
        r.z = c1.x * scale; r.w = c1.y * scale;
        *(float4*)(g_S0 + ((size_t)h * NA + a) * NA + n) = r;
    }
}

// ---------------- per-(b,h,n): online max + env-weighted exp-sum -> C ----------------
__global__ void __launch_bounds__(256) stat_kernel(
    const float* __restrict__ envelope, const int* __restrict__ edge_map,
    const int* __restrict__ atom_index)
{
    const int b = blockIdx.z, h = blockIdx.y;
    const int n = blockIdx.x * 256 + threadIdx.x;
    const int s0 = g_seg[b], s1 = g_seg[b + 1];
    __shared__ float s_env[128];
    __shared__ int   s_a[128];
    __shared__ int   s_mp[128];
    const float* S0h = g_S0 + (size_t)h * NA * NA;
    float m = -INFINITY, s = 0.f;
    for (int c = s0; c < s1; c += 128) {
        const int cnt = min(128, s1 - c);
        __syncthreads();
        if (threadIdx.x < cnt) {
            int e = c + threadIdx.x;
            int mp = edge_map[e];
            s_a[threadIdx.x]   = atom_index[e];
            s_mp[threadIdx.x]  = mp;
            s_env[threadIdx.x] = envelope[mp];
        }
        __syncthreads();
        for (int i = 0; i < cnt; i++) {
            float x = S0h[(size_t)s_a[i] * NA + n] + g_biasT[(size_t)s_mp[i] * NA + n];
            float env = s_env[i];
            if (x > m) { s = s * expf(m - x) + env; m = x; }
            else       { s += env * expf(x - m); }
        }
    }
    float cval = (m == -INFINITY) ? 0.f : expf(-m) / (s + 1e-16f);
    g_C[((size_t)b * NH + h) * NA + n] = cval;
}

// ---------------- W2[h][a][n] = exp(S0)*sum_{e->a} env2_e*exp(bias_e[n])*C[b_e,h,n] ----
__global__ void __launch_bounds__(128) w2_kernel(
    const int* __restrict__ edge_map, const int* __restrict__ batch_index,
    const float* __restrict__ envelope)
{
    const int a = blockIdx.y;
    const int n = blockIdx.x * 128 + threadIdx.x;
    const int o0 = g_off[a], o1 = g_off[a + 1];
    float acc[NH] = {};
    for (int j = o0; j < o1; j++) {
        int e  = g_csr[j];               // broadcast loads
        int mp = edge_map[e];
        int bb = batch_index[e];
        float env = envelope[mp];
        float t = env * env * expf(g_biasT[(size_t)mp * NA + n]);
        const float* Cb = g_C + (size_t)bb * NH * NA + n;
#pragma unroll
        for (int h = 0; h < NH; h++)
            acc[h] += t * Cb[(size_t)h * NA];
    }
#pragma unroll
    for (int h = 0; h < NH; h++) {
        const size_t idx = ((size_t)h * NA + a) * NA + n;
        g_W2[idx] = expf(g_S0[idx]) * acc[h];
    }
}

// ---------------- out[n][h*128+d] = sum_a W2[h][a][n] * vp[a][h*128+d] ----------------
__global__ void __launch_bounds__(256) out2_kernel()
{
    __shared__ float As[16][68];   // W2 tile: [k=a][n]
    __shared__ float Bs[16][68];   // V tile:  [k=a][d]
    const int h  = blockIdx.z;
    const int d0 = blockIdx.x * 64;
    const int n0 = blockIdx.y * 64;
    const int tid = threadIdx.x;
    const int tx = tid & 15, ty = tid >> 4;
    const int lkk = tid >> 4, lc = (tid & 15) * 4;   // load coords: row kk, 4 cols
    unsigned long long acc[4][2] = {};

    const float* Wbase = g_W2 + (size_t)h * NA * NA;
    const float* Vbase = g_vp + h * HD;
    for (int k0 = 0; k0 < NA; k0 += 16) {
        *(float4*)&As[lkk][lc] = *(const float4*)(Wbase + (size_t)(k0 + lkk) * NA + n0 + lc);
        *(float4*)&Bs[lkk][lc] = *(const float4*)(Vbase + (size_t)(k0 + lkk) * HC + d0 + lc);
        __syncthreads();
#pragma unroll
        for (int kk = 0; kk < 16; kk++) {
            float4 av = *(const float4*)&As[kk][ty * 4];   // 4 n values
            unsigned long long b0 = *(const unsigned long long*)&Bs[kk][tx * 4];
            unsigned long long b1 = *(const unsigned long long*)&Bs[kk][tx * 4 + 2];
            unsigned long long a0 = pack2(av.x, av.x), a1 = pack2(av.y, av.y);
            unsigned long long a2 = pack2(av.z, av.z), a3 = pack2(av.w, av.w);
            fma2(acc[0][0], a0, b0); fma2(acc[0][1], a0, b1);
            fma2(acc[1][0], a1, b0); fma2(acc[1][1], a1, b1);
            fma2(acc[2][0], a2, b0); fma2(acc[2][1], a2, b1);
            fma2(acc[3][0], a3, b0); fma2(acc[3][1], a3, b1);
        }
        __syncthreads();
    }
    const int d = d0 + tx * 4;
#pragma unroll
    for (int i = 0; i < 4; i++) {
        float2 c0 = unpack2(acc[i][0]), c1 = unpack2(acc[i][1]);
        float4 r; r.x = c0.x; r.y = c0.y; r.z = c1.x; r.w = c1.y;
        *(float4*)(g_attn + (size_t)(n0 + ty * 4 + i) * HC + h * HD + d) = r;
    }
}

// ---------------- LayerNorm over H_CH per row ----------------
__global__ void __launch_bounds__(256) ln_kernel(
    const float* __restrict__ ln_g, const float* __restrict__ ln_b)
{
    const int n = blockIdx.x;
    const int tid = threadIdx.x;
    const float* x = g_attn + (size_t)n * HC;
    float s = 0.f, s2 = 0.f;
    for (int i = tid; i < HC; i += 256) {
        float v = x[i];
        s += v; s2 += v * v;
    }
#pragma unroll
    for (int o = 16; o > 0; o >>= 1) {
        s  += __shfl_xor_sync(0xffffffffu, s, o);
        s2 += __shfl_xor_sync(0xffffffffu, s2, o);
    }
    __shared__ float ws[8], ws2[8], stats[2];
    if ((tid & 31) == 0) { ws[tid >> 5] = s; ws2[tid >> 5] = s2; }
    __syncthreads();
    if (tid == 0) {
        float a = 0.f, b = 0.f;
#pragma unroll
        for (int i = 0; i < 8; i++) { a += ws[i]; b += ws2[i]; }
        float mean = a * (1.f / HC);
        float var  = b * (1.f / HC) - mean * mean;
        stats[0] = mean;
        stats[1] = rsqrtf(var + 1e-7f);
    }
    __syncthreads();
    const float mean = stats[0], inv = stats[1];
    for (int i = tid; i < HC; i += 256) {
        g_ln[(size_t)n * HC + i] = (x[i] - mean) * inv * ln_g[i] + ln_b[i];
    }
}

// ---------------- launch ----------------
extern "C" void kernel_launch(void* const* d_in, const int* in_sizes, int n_in,
                              void* d_out, int out_size)
{
    const float* q         = (const float*)d_in[0];
    const float* k         = (const float*)d_in[1];
    const float* v         = (const float*)d_in[2];
    const float* envelope  = (const float*)d_in[3];
    const float* attn_bias = (const float*)d_in[4];
    const float* Wq        = (const float*)d_in[5];
    const float* bq        = (const float*)d_in[6];
    const float* Wk        = (const float*)d_in[7];
    const float* bk        = (const float*)d_in[8];
    const float* Wv        = (const float*)d_in[9];
    const float* bv        = (const float*)d_in[10];
    const float* ln_g      = (const float*)d_in[11];
    const float* ln_b      = (const float*)d_in[12];
    const float* Wo        = (const float*)d_in[13];
    const float* bo        = (const float*)d_in[14];
    const int* atom_index  = (const int*)d_in[15];
    const int* batch_index = (const int*)d_in[16];
    const int* edge_map    = (const int*)d_in[17];
    float* out = (float*)d_out;

    float *qp, *kp, *vp, *lnp;
    cudaGetSymbolAddress((void**)&qp, g_qp);
    cudaGetSymbolAddress((void**)&kp, g_kp);
    cudaGetSymbolAddress((void**)&vp, g_vp);
    cudaGetSymbolAddress((void**)&lnp, g_ln);

    // projections: [1024,512] @ [1024,512]^T -> [1024,1024]
    gemm_abT<<<dim3(HC / 64, NA / 64), 256>>>(q, Wq, bq, qp, NA, HC, INC);
    gemm_abT<<<dim3(HC / 64, NA / 64), 256>>>(k, Wk, bk, kp, NA, HC, INC);
    gemm_abT<<<dim3(HC / 64, NA / 64), 256>>>(v, Wv, bv, vp, NA, HC, INC);

    transpose_bias<<<dim3(MM / 32, NA / 32), dim3(32, 8)>>>(attn_bias);
    seg_kernel<<<1, 128>>>(batch_index);

    // CSR: group edges by atom (deterministic)
    deg_kernel<<<NA / 8, 256>>>(atom_index);
    scan_kernel<<<1, 1024>>>();
    fill_kernel<<<NA / 8, 256>>>(atom_index);

    // dense per-atom scores + softmax stats + per-atom weights + dense output
    s0_kernel<<<dim3(NA / 64, NA / 64, NH), 256>>>();
    stat_kernel<<<dim3(NA / 256, NH, BB), 256>>>(envelope, edge_map, atom_index);
    w2_kernel<<<dim3(NA / 128, NA), 128>>>(edge_map, batch_index, envelope);
    out2_kernel<<<dim3(HD / 64, NA / 64, NH), 256>>>();

    ln_kernel<<<NA, 256>>>(ln_g, ln_b);

    // final: [1024,1024] @ [512,1024]^T -> [1024,512]
    gemm_abT<<<dim3(INC / 64, NA / 64), 256>>>(lnp, Wo, bo, out, NA, INC, HC);
}

// round 6
// speedup vs baseline: 3.9029x; 1.0919x over previous
#include <cuda_runtime.h>
#include <math.h>

// Problem constants
#define NA  1024   // N atoms
#define EE  8192   // E edges
#define MM  8192   // M envelope table
#define BB  64     // B batches
#define INC 512    // IN_CH
#define HC  1024   // H_CH
#define NH  8      // heads
#define HD  128    // head dim

// ---------------- scratch ----------------
__device__ float g_proj[3 * NA * HC];               // qp / kp / vp
__device__ float g_EB[(size_t)MM * NA];             // 32 MB: exp(attn_bias^T)[m][n]
__device__ float g_ES0[(size_t)NH * NA * NA];       // 32 MB: exp(S0)[h][a][n]
__device__ float g_W2[(size_t)NH * NA * NA];        // 32 MB
__device__ float g_C[(size_t)BB * NH * NA];         // 2 MB: 1/(sum+eps)
__device__ float g_attn[NA * HC];
__device__ float g_ln[NA * HC];
__device__ int   g_seg[BB + 1];
__device__ int   g_deg[NA];
__device__ int   g_off[NA + 1];
__device__ int   g_csr[EE];

// ---------------- packed f32x2 helpers (sm_100+) ----------------
__device__ __forceinline__ unsigned long long pack2(float x, float y) {
    unsigned long long r;
    asm("mov.b64 %0, {%1, %2};" : "=l"(r) : "f"(x), "f"(y));
    return r;
}
__device__ __forceinline__ float2 unpack2(unsigned long long v) {
    float2 r;
    asm("mov.b64 {%0, %1}, %2;" : "=f"(r.x), "=f"(r.y) : "l"(v));
    return r;
}
__device__ __forceinline__ void fma2(unsigned long long& d, unsigned long long a,
                                     unsigned long long b) {
    asm("fma.rn.f32x2 %0, %1, %2, %0;" : "+l"(d) : "l"(a), "l"(b));
}

// ============ 128x64-tile GEMM, row-major A[M,K], B[N,K]; C = A@B^T ============
// 256 threads, 8x4 outputs/thread (as 8x2 f32x2). Optional bias or exp(scale*x).
__device__ __forceinline__ void gemm_rm_impl(
    const float* __restrict__ A, int lda,
    const float* __restrict__ B, int ldb,
    const float* __restrict__ bias, float* __restrict__ C, int ldc,
    int K, float scale, bool do_exp)
{
    __shared__ float As[16][132];
    __shared__ float Bs[16][68];
    const int m0 = blockIdx.y * 128;
    const int n0 = blockIdx.x * 64;
    const int tid = threadIdx.x;
    const int tx = tid & 15, ty = tid >> 4;
    const int lrA = tid >> 1, lkA = (tid & 1) * 8;
    const int lrB = tid & 63, lkB = (tid >> 6) * 4;
    unsigned long long acc[8][2] = {};

    for (int k0 = 0; k0 < K; k0 += 16) {
        float4 a0 = *(const float4*)(A + (size_t)(m0 + lrA) * lda + k0 + lkA);
        float4 a1 = *(const float4*)(A + (size_t)(m0 + lrA) * lda + k0 + lkA + 4);
        float4 b  = *(const float4*)(B + (size_t)(n0 + lrB) * ldb + k0 + lkB);
        As[lkA + 0][lrA] = a0.x; As[lkA + 1][lrA] = a0.y;
        As[lkA + 2][lrA] = a0.z; As[lkA + 3][lrA] = a0.w;
        As[lkA + 4][lrA] = a1.x; As[lkA + 5][lrA] = a1.y;
        As[lkA + 6][lrA] = a1.z; As[lkA + 7][lrA] = a1.w;
        Bs[lkB + 0][lrB] = b.x;  Bs[lkB + 1][lrB] = b.y;
        Bs[lkB + 2][lrB] = b.z;  Bs[lkB + 3][lrB] = b.w;
        __syncthreads();
#pragma unroll
        for (int kk = 0; kk < 16; kk++) {
            float4 av0 = *(const float4*)&As[kk][ty * 8];
            float4 av1 = *(const float4*)&As[kk][ty * 8 + 4];
            unsigned long long b0 = *(const unsigned long long*)&Bs[kk][tx * 4];
            unsigned long long b1 = *(const unsigned long long*)&Bs[kk][tx * 4 + 2];
            unsigned long long p;
            p = pack2(av0.x, av0.x); fma2(acc[0][0], p, b0); fma2(acc[0][1], p, b1);
            p = pack2(av0.y, av0.y); fma2(acc[1][0], p, b0); fma2(acc[1][1], p, b1);
            p = pack2(av0.z, av0.z); fma2(acc[2][0], p, b0); fma2(acc[2][1], p, b1);
            p = pack2(av0.w, av0.w); fma2(acc[3][0], p, b0); fma2(acc[3][1], p, b1);
            p = pack2(av1.x, av1.x); fma2(acc[4][0], p, b0); fma2(acc[4][1], p, b1);
            p = pack2(av1.y, av1.y); fma2(acc[5][0], p, b0); fma2(acc[5][1], p, b1);
            p = pack2(av1.z, av1.z); fma2(acc[6][0], p, b0); fma2(acc[6][1], p, b1);
            p = pack2(av1.w, av1.w); fma2(acc[7][0], p, b0); fma2(acc[7][1], p, b1);
        }
        __syncthreads();
    }
    const int n = n0 + tx * 4;
    float4 bb = make_float4(0.f, 0.f, 0.f, 0.f);
    if (bias) bb = *(const float4*)(bias + n);
#pragma unroll
    for (int i = 0; i < 8; i++) {
        float2 c0 = unpack2(acc[i][0]), c1 = unpack2(acc[i][1]);
        float4 r;
        if (do_exp) {
            r.x = __expf(c0.x * scale); r.y = __expf(c0.y * scale);
            r.z = __expf(c1.x * scale); r.w = __expf(c1.y * scale);
        } else {
            r.x = c0.x + bb.x; r.y = c0.y + bb.y;
            r.z = c1.x + bb.z; r.w = c1.y + bb.w;
        }
        *(float4*)(C + (size_t)(m0 + ty * 8 + i) * ldc + n) = r;
    }
}

// fused q/k/v projections, blockIdx.z selects which
__global__ void __launch_bounds__(256) qkv_kernel(
    const float* __restrict__ q, const float* __restrict__ k, const float* __restrict__ v,
    const float* __restrict__ Wq, const float* __restrict__ Wk, const float* __restrict__ Wv,
    const float* __restrict__ bq, const float* __restrict__ bk, const float* __restrict__ bv)
{
    const int z = blockIdx.z;
    const float* A  = (z == 0) ? q  : (z == 1) ? k  : v;
    const float* B  = (z == 0) ? Wq : (z == 1) ? Wk : Wv;
    const float* bi = (z == 0) ? bq : (z == 1) ? bk : bv;
    float* C = g_proj + (size_t)z * NA * HC;
    gemm_rm_impl(A, INC, B, INC, bi, C, HC, INC, 0.f, false);
}

// ES0[h][a][n] = exp(dot(k_a, q_n)/sqrt(D))
__global__ void __launch_bounds__(256) s0_kernel()
{
    const int h = blockIdx.z;
    gemm_rm_impl(g_proj + 1 * NA * HC + h * HD, HC,
                 g_proj + 0 * NA * HC + h * HD, HC,
                 nullptr, g_ES0 + (size_t)h * NA * NA, NA, HD,
                 0.08838834764831845f, true);
}

// ---------------- old 64x64 GEMM (kept for the final 1024x512 GEMM) ----------------
__global__ void __launch_bounds__(256) gemm_abT(
    const float* __restrict__ A, const float* __restrict__ B,
    const float* __restrict__ bias, float* __restrict__ C,
    int M, int N, int K)
{
    __shared__ float As[16][68];
    __shared__ float Bs[16][68];
    const int m0 = blockIdx.y * 64, n0 = blockIdx.x * 64;
    const int tid = threadIdx.x;
    const int tx = tid & 15, ty = tid >> 4;
    const int lr = tid >> 2, lk = (tid & 3) << 2;
    unsigned long long acc[4][2] = {};

    for (int k0 = 0; k0 < K; k0 += 16) {
        float4 a = *(const float4*)(A + (size_t)(m0 + lr) * K + k0 + lk);
        float4 b = *(const float4*)(B + (size_t)(n0 + lr) * K + k0 + lk);
        As[lk + 0][lr] = a.x; As[lk + 1][lr] = a.y; As[lk + 2][lr] = a.z; As[lk + 3][lr] = a.w;
        Bs[lk + 0][lr] = b.x; Bs[lk + 1][lr] = b.y; Bs[lk + 2][lr] = b.z; Bs[lk + 3][lr] = b.w;
        __syncthreads();
#pragma unroll
        for (int kk = 0; kk < 16; kk++) {
            float4 av = *(const float4*)&As[kk][ty * 4];
            unsigned long long b0 = *(const unsigned long long*)&Bs[kk][tx * 4];
            unsigned long long b1 = *(const unsigned long long*)&Bs[kk][tx * 4 + 2];
            unsigned long long a0 = pack2(av.x, av.x), a1 = pack2(av.y, av.y);
            unsigned long long a2 = pack2(av.z, av.z), a3 = pack2(av.w, av.w);
            fma2(acc[0][0], a0, b0); fma2(acc[0][1], a0, b1);
            fma2(acc[1][0], a1, b0); fma2(acc[1][1], a1, b1);
            fma2(acc[2][0], a2, b0); fma2(acc[2][1], a2, b1);
            fma2(acc[3][0], a3, b0); fma2(acc[3][1], a3, b1);
        }
        __syncthreads();
    }
    const int n = n0 + tx * 4;
    float4 bb = *(const float4*)(bias + n);
#pragma unroll
    for (int i = 0; i < 4; i++) {
        float2 c0 = unpack2(acc[i][0]), c1 = unpack2(acc[i][1]);
        float4 r;
        r.x = c0.x + bb.x; r.y = c0.y + bb.y; r.z = c1.x + bb.z; r.w = c1.y + bb.w;
        *(float4*)(C + (size_t)(m0 + ty * 4 + i) * N + n) = r;
    }
}

// ---------------- EB[m][n] = exp(attn_bias[n][m]) (fused transpose+exp) ----------------
__global__ void __launch_bounds__(256) transpose_exp(const float* __restrict__ src)
{
    __shared__ float tile[64][65];
    const int m0 = blockIdx.x * 64, n0 = blockIdx.y * 64;
    const int tid = threadIdx.x;
    const int r = tid >> 4, c4 = (tid & 15) * 4;
#pragma unroll
    for (int p = 0; p < 4; p++) {
        float4 vld = *(const float4*)(src + (size_t)(n0 + r + p * 16) * MM + m0 + c4);
        tile[r + p * 16][c4 + 0] = vld.x;
        tile[r + p * 16][c4 + 1] = vld.y;
        tile[r + p * 16][c4 + 2] = vld.z;
        tile[r + p * 16][c4 + 3] = vld.w;
    }
    __syncthreads();
#pragma unroll
    for (int p = 0; p < 4; p++) {
        const int mloc = r + p * 16;
        float4 o;
        o.x = __expf(tile[c4 + 0][mloc]);
        o.y = __expf(tile[c4 + 1][mloc]);
        o.z = __expf(tile[c4 + 2][mloc]);
        o.w = __expf(tile[c4 + 3][mloc]);
        *(float4*)(g_EB + (size_t)(m0 + mloc) * NA + n0 + c4) = o;
    }
}

// ---------------- segment boundaries (batch_index is sorted) ----------------
__global__ void seg_kernel(const int* __restrict__ batch_index)
{
    const int b = threadIdx.x;
    if (b <= BB) {
        int lo = 0, hi = EE;
        while (lo < hi) {
            int mid = (lo + hi) >> 1;
            if (batch_index[mid] < b) lo = mid + 1; else hi = mid;
        }
        g_seg[b] = lo;
    }
}

// ---------------- CSR build: group edges by atom (deterministic, e-order) ------------
__global__ void __launch_bounds__(256) deg_kernel(const int* __restrict__ atom_index)
{
    const int w = (blockIdx.x * 256 + threadIdx.x) >> 5;
    const int lane = threadIdx.x & 31;
    int cnt = 0;
    for (int base = 0; base < EE; base += 32) {
        int a = atom_index[base + lane];
        unsigned mask = __ballot_sync(0xffffffffu, a == w);
        cnt += __popc(mask);
    }
    if (lane == 0) g_deg[w] = cnt;
}

__global__ void __launch_bounds__(1024) scan_kernel()
{
    __shared__ int buf[1024];
    const int tid = threadIdx.x;
    buf[tid] = g_deg[tid];
    __syncthreads();
    for (int s = 1; s < 1024; s <<= 1) {
        int v = (tid >= s) ? buf[tid - s] : 0;
        __syncthreads();
        buf[tid] += v;
        __syncthreads();
    }
    g_off[tid + 1] = buf[tid];
    if (tid == 0) g_off[0] = 0;
}

__global__ void __launch_bounds__(256) fill_kernel(const int* __restrict__ atom_index)
{
    const int w = (blockIdx.x * 256 + threadIdx.x) >> 5;
    const int lane = threadIdx.x & 31;
    int o = g_off[w];
    for (int base = 0; base < EE; base += 32) {
        int a = atom_index[base + lane];
        bool match = (a == w);
        unsigned mask = __ballot_sync(0xffffffffu, match);
        int rank = __popc(mask & ((1u << lane) - 1));
        if (match) g_csr[o + rank] = base + lane;
        o += __popc(mask);
    }
}

// ---- C[b][h][n] = 1 / (sum_{e in b} env_e * EB[mp_e][n] * ES0[h][a_e][n] + 1e-16) ----
__global__ void __launch_bounds__(256) csum_kernel(
    const int* __restrict__ atom_index, const int* __restrict__ edge_map,
    const float* __restrict__ envelope)
{
    const int b = blockIdx.y;
    const int n = blockIdx.x * 256 + threadIdx.x;
    const int s0 = g_seg[b], s1 = g_seg[b + 1];
    __shared__ int   s_a[128], s_mp[128];
    __shared__ float s_env[128];
    float acc[NH] = {};
    for (int c = s0; c < s1; c += 128) {
        const int cnt = min(128, s1 - c);
        __syncthreads();
        if (threadIdx.x < cnt) {
            int e = c + threadIdx.x;
            int mp = edge_map[e];
            s_a[threadIdx.x]   = atom_index[e];
            s_mp[threadIdx.x]  = mp;
            s_env[threadIdx.x] = envelope[mp];
        }
        __syncthreads();
        for (int i = 0; i < cnt; i++) {
            float val = s_env[i] * g_EB[(size_t)s_mp[i] * NA + n];
            const float* es = g_ES0 + (size_t)s_a[i] * NA + n;
#pragma unroll
            for (int h = 0; h < NH; h++)
                acc[h] += val * es[(size_t)h * NA * NA];
        }
    }
#pragma unroll
    for (int h = 0; h < NH; h++)
        g_C[((size_t)b * NH + h) * NA + n] = 1.f / (acc[h] + 1e-16f);
}

// ---- W2[h][a][n] = ES0[h][a][n] * sum_{e->a} env_e^2 * EB[mp_e][n] * C[b_e][h][n] ----
__global__ void __launch_bounds__(128) w2_kernel(
    const int* __restrict__ edge_map, const int* __restrict__ batch_index,
    const float* __restrict__ envelope)
{
    const int a = blockIdx.y;
    const int n = blockIdx.x * 128 + threadIdx.x;
    const int o0 = g_off[a], o1 = g_off[a + 1];
    float acc[NH] = {};
    for (int j = o0; j < o1; j++) {
        int e  = g_csr[j];
        int mp = edge_map[e];
        int bb = batch_index[e];
        float env = envelope[mp];
        float t = env * env * g_EB[(size_t)mp * NA + n];
        const float* Cb = g_C + (size_t)bb * NH * NA + n;
#pragma unroll
        for (int h = 0; h < NH; h++)
            acc[h] += t * Cb[(size_t)h * NA];
    }
#pragma unroll
    for (int h = 0; h < NH; h++) {
        const size_t idx = ((size_t)h * NA + a) * NA + n;
        g_W2[idx] = g_ES0[idx] * acc[h];
    }
}

// ---------------- out[n][h*128+d] = sum_a W2[h][a][n] * vp[a][h*128+d] ----------------
// A operand (W2) is k-major: straight float4 tile loads, no transpose.
__global__ void __launch_bounds__(256) out2_kernel()
{
    __shared__ float As[16][132];   // [k][n]
    __shared__ float Bs[16][68];    // [k][d]
    const int h  = blockIdx.z;
    const int d0 = blockIdx.x * 64;
    const int n0 = blockIdx.y * 128;
    const int tid = threadIdx.x;
    const int tx = tid & 15, ty = tid >> 4;
    const int lk = tid >> 4, lcA = (tid & 15) * 8, lcB = (tid & 15) * 4;
    const float* Wb = g_W2 + (size_t)h * NA * NA;
    const float* Vb = g_proj + 2 * NA * HC + h * HD;
    unsigned long long acc[8][2] = {};

    for (int k0 = 0; k0 < NA; k0 += 16) {
        *(float4*)&As[lk][lcA]     = *(const float4*)(Wb + (size_t)(k0 + lk) * NA + n0 + lcA);
        *(float4*)&As[lk][lcA + 4] = *(const float4*)(Wb + (size_t)(k0 + lk) * NA + n0 + lcA + 4);
        *(float4*)&Bs[lk][lcB]     = *(const float4*)(Vb + (size_t)(k0 + lk) * HC + d0 + lcB);
        __syncthreads();
#pragma unroll
        for (int kk = 0; kk < 16; kk++) {
            float4 av0 = *(const float4*)&As[kk][ty * 8];
            float4 av1 = *(const float4*)&As[kk][ty * 8 + 4];
            unsigned long long b0 = *(const unsigned long long*)&Bs[kk][tx * 4];
            unsigned long long b1 = *(const unsigned long long*)&Bs[kk][tx * 4 + 2];
            unsigned long long p;
            p = pack2(av0.x, av0.x); fma2(acc[0][0], p, b0); fma2(acc[0][1], p, b1);
            p = pack2(av0.y, av0.y); fma2(acc[1][0], p, b0); fma2(acc[1][1], p, b1);
            p = pack2(av0.z, av0.z); fma2(acc[2][0], p, b0); fma2(acc[2][1], p, b1);
            p = pack2(av0.w, av0.w); fma2(acc[3][0], p, b0); fma2(acc[3][1], p, b1);
            p = pack2(av1.x, av1.x); fma2(acc[4][0], p, b0); fma2(acc[4][1], p, b1);
            p = pack2(av1.y, av1.y); fma2(acc[5][0], p, b0); fma2(acc[5][1], p, b1);
            p = pack2(av1.z, av1.z); fma2(acc[6][0], p, b0); fma2(acc[6][1], p, b1);
            p = pack2(av1.w, av1.w); fma2(acc[7][0], p, b0); fma2(acc[7][1], p, b1);
        }
        __syncthreads();
    }
#pragma unroll
    for (int i = 0; i < 8; i++) {
        float2 c0 = unpack2(acc[i][0]), c1 = unpack2(acc[i][1]);
        float4 r; r.x = c0.x; r.y = c0.y; r.z = c1.x; r.w = c1.y;
        *(float4*)(g_attn + (size_t)(n0 + ty * 8 + i) * HC + h * HD + d0 + tx * 4) = r;
    }
}

// ---------------- LayerNorm over H_CH per row ----------------
__global__ void __launch_bounds__(256) ln_kernel(
    const float* __restrict__ ln_g, const float* __restrict__ ln_b)
{
    const int n = blockIdx.x;
    const int tid = threadIdx.x;
    const float* x = g_attn + (size_t)n * HC;
    float s = 0.f, s2 = 0.f;
    for (int i = tid; i < HC; i += 256) {
        float v = x[i];
        s += v; s2 += v * v;
    }
#pragma unroll
    for (int o = 16; o > 0; o >>= 1) {
        s  += __shfl_xor_sync(0xffffffffu, s, o);
        s2 += __shfl_xor_sync(0xffffffffu, s2, o);
    }
    __shared__ float ws[8], ws2[8], stats[2];
    if ((tid & 31) == 0) { ws[tid >> 5] = s; ws2[tid >> 5] = s2; }
    __syncthreads();
    if (tid == 0) {
        float a = 0.f, b = 0.f;
#pragma unroll
        for (int i = 0; i < 8; i++) { a += ws[i]; b += ws2[i]; }
        float mean = a * (1.f / HC);
        float var  = b * (1.f / HC) - mean * mean;
        stats[0] = mean;
        stats[1] = rsqrtf(var + 1e-7f);
    }
    __syncthreads();
    const float mean = stats[0], inv = stats[1];
    for (int i = tid; i < HC; i += 256) {
        g_ln[(size_t)n * HC + i] = (x[i] - mean) * inv * ln_g[i] + ln_b[i];
    }
}

// ---------------- launch ----------------
extern "C" void kernel_launch(void* const* d_in, const int* in_sizes, int n_in,
                              void* d_out, int out_size)
{
    const float* q         = (const float*)d_in[0];
    const float* k         = (const float*)d_in[1];
    const float* v         = (const float*)d_in[2];
    const float* envelope  = (const float*)d_in[3];
    const float* attn_bias = (const float*)d_in[4];
    const float* Wq        = (const float*)d_in[5];
    const float* bq        = (const float*)d_in[6];
    const float* Wk        = (const float*)d_in[7];
    const float* bk        = (const float*)d_in[8];
    const float* Wv        = (const float*)d_in[9];
    const float* bv        = (const float*)d_in[10];
    const float* ln_g      = (const float*)d_in[11];
    const float* ln_b      = (const float*)d_in[12];
    const float* Wo        = (const float*)d_in[13];
    const float* bo        = (const float*)d_in[14];
    const int* atom_index  = (const int*)d_in[15];
    const int* batch_index = (const int*)d_in[16];
    const int* edge_map    = (const int*)d_in[17];
    float* out = (float*)d_out;

    float* lnp;
    cudaGetSymbolAddress((void**)&lnp, g_ln);

    // fused q/k/v projections: 3 x [1024,512]@[1024,512]^T
    qkv_kernel<<<dim3(HC / 64, NA / 128, 3), 256>>>(q, k, v, Wq, Wk, Wv, bq, bk, bv);

    transpose_exp<<<dim3(MM / 64, NA / 64), 256>>>(attn_bias);
    seg_kernel<<<1, 128>>>(batch_index);
    deg_kernel<<<NA / 8, 256>>>(atom_index);
    scan_kernel<<<1, 1024>>>();
    fill_kernel<<<NA / 8, 256>>>(atom_index);

    // exp(scores) dense per atom, softmax denominators, per-atom weights, output
    s0_kernel<<<dim3(NA / 64, NA / 128, NH), 256>>>();
    csum_kernel<<<dim3(NA / 256, BB), 256>>>(atom_index, edge_map, envelope);
    w2_kernel<<<dim3(NA / 128, NA), 128>>>(edge_map, batch_index, envelope);
    out2_kernel<<<dim3(HD / 64, NA / 128, NH), 256>>>();

    ln_kernel<<<NA, 256>>>(ln_g, ln_b);

    // final: [1024,1024] @ [512,1024]^T -> [1024,512]
    gemm_abT<<<dim3(INC / 64, NA / 64), 256>>>(lnp, Wo, bo, out, NA, INC, HC);
}

// round 9
// speedup vs baseline: 4.8227x; 1.2357x over previous
#include <cuda_runtime.h>
#include <cuda_bf16.h>
#include <mma.h>
#include <cstdint>
#include <math.h>

using namespace nvcuda;

// Problem constants
#define NA  1024   // N atoms
#define EE  8192   // E edges
#define MM  8192   // M envelope table
#define BB  64     // B batches
#define INC 512    // IN_CH
#define HC  1024   // H_CH
#define NH  8      // heads
#define HD  128    // head dim

#define SEG 524288 // elements per split slab (all 7 external operands are 512K elems)

// ---------------- scratch ----------------
__device__ __nv_bfloat16 g_split_h[7 * SEG];     // q,k,v,Wq,Wk,Wv,Wo (hi)
__device__ __nv_bfloat16 g_split_l[7 * SEG];     // (lo)
__device__ __nv_bfloat16 g_ph[3 * NA * HC];      // qp/kp/vp hi
__device__ __nv_bfloat16 g_pl[3 * NA * HC];      // qp/kp/vp lo
__device__ __nv_bfloat16 g_lnh[NA * HC];
__device__ __nv_bfloat16 g_lnl[NA * HC];
__device__ __nv_bfloat16 g_W2h[(size_t)NH * NA * NA];
__device__ __nv_bfloat16 g_W2l[(size_t)NH * NA * NA];
__device__ float g_EB[(size_t)MM * NA];          // exp(attn_bias^T)[m][n]
__device__ float g_ES0[(size_t)NH * NA * NA];    // exp(S0)[h][a][n]
__device__ float g_C[BB * NH * NA];
__device__ float g_attn[NA * HC];
__device__ int   g_seg[BB + 1];
__device__ int   g_deg[NA];
__device__ int   g_off[NA + 1];
__device__ int   g_csr[EE];

__device__ __forceinline__ void split2(float v, __nv_bfloat16& h, __nv_bfloat16& l) {
    h = __float2bfloat16(v);
    l = __float2bfloat16(v - __bfloat162float(h));
}

// ---------------- split the 7 external fp32 operands into hi/lo bf16 ----------------
__global__ void __launch_bounds__(256) split_kernel(
    const float* __restrict__ q,  const float* __restrict__ k,  const float* __restrict__ v,
    const float* __restrict__ Wq, const float* __restrict__ Wk, const float* __restrict__ Wv,
    const float* __restrict__ Wo)
{
    const float* srcs[7] = {q, k, v, Wq, Wk, Wv, Wo};
    const float* s = srcs[blockIdx.y];
    const size_t base = (size_t)blockIdx.y * SEG;
    const int i0 = (blockIdx.x * 256 + threadIdx.x) * 4;
    float4 f = *(const float4*)(s + i0);
    union { __nv_bfloat16 b[4]; uint2 u; } H, L;
    split2(f.x, H.b[0], L.b[0]);
    split2(f.y, H.b[1], L.b[1]);
    split2(f.z, H.b[2], L.b[2]);
    split2(f.w, H.b[3], L.b[3]);
    *(uint2*)(g_split_h + base + i0) = H.u;
    *(uint2*)(g_split_l + base + i0) = L.u;
}

// ================= wmma GEMM cores =================
// Block tile 128x64, 256 threads (8 warps), warp tile 32x32, K chunk 32.
// Split bf16: C += Ah@Bh^T + Ah@Bl^T + Al@Bh^T   (fp32 accum)

typedef wmma::fragment<wmma::accumulator, 16, 16, 16, float> FragC;

// A [M,K] row-major, B [N,K] row-major (i.e. C = A @ B^T)
__device__ __forceinline__ void gemm_rr(
    const __nv_bfloat16* __restrict__ Ah, const __nv_bfloat16* __restrict__ Al, int lda, int m0,
    const __nv_bfloat16* __restrict__ Bh, const __nv_bfloat16* __restrict__ Bl, int ldb, int n0,
    int K, float* smem, FragC c[2][2])
{
    const int tid = threadIdx.x;
    const int wid = tid >> 5;
    const int wm0 = (wid >> 1) * 32;
    const int wn0 = (wid & 1) * 32;
    __nv_bfloat16* sAh = (__nv_bfloat16*)smem;            // [128][40]
    __nv_bfloat16* sAl = sAh + 128 * 40;
    __nv_bfloat16* sBh = sAl + 128 * 40;                  // [64][40]
    __nv_bfloat16* sBl = sBh + 64 * 40;
#pragma unroll
    for (int i = 0; i < 2; i++)
#pragma unroll
        for (int j = 0; j < 2; j++) wmma::fill_fragment(c[i][j], 0.f);

    const int rA = tid >> 1, cA = (tid & 1) * 16;
    const int rB = tid >> 2, cB = (tid & 3) * 8;
    for (int k0 = 0; k0 < K; k0 += 32) {
        const __nv_bfloat16* pAh = Ah + (size_t)(m0 + rA) * lda + k0 + cA;
        const __nv_bfloat16* pAl = Al + (size_t)(m0 + rA) * lda + k0 + cA;
        *(uint4*)(sAh + rA * 40 + cA)     = *(const uint4*)pAh;
        *(uint4*)(sAh + rA * 40 + cA + 8) = *(const uint4*)(pAh + 8);
        *(uint4*)(sAl + rA * 40 + cA)     = *(const uint4*)pAl;
        *(uint4*)(sAl + rA * 40 + cA + 8) = *(const uint4*)(pAl + 8);
        *(uint4*)(sBh + rB * 40 + cB) = *(const uint4*)(Bh + (size_t)(n0 + rB) * ldb + k0 + cB);
        *(uint4*)(sBl + rB * 40 + cB) = *(const uint4*)(Bl + (size_t)(n0 + rB) * ldb + k0 + cB);
        __syncthreads();
#pragma unroll
        for (int kk = 0; kk < 32; kk += 16) {
            wmma::fragment<wmma::matrix_a, 16, 16, 16, __nv_bfloat16, wmma::row_major> aH[2], aL[2];
            wmma::fragment<wmma::matrix_b, 16, 16, 16, __nv_bfloat16, wmma::col_major> bH[2], bL[2];
#pragma unroll
            for (int i = 0; i < 2; i++) {
                wmma::load_matrix_sync(aH[i], sAh + (wm0 + 16 * i) * 40 + kk, 40);
                wmma::load_matrix_sync(aL[i], sAl + (wm0 + 16 * i) * 40 + kk, 40);
            }
#pragma unroll
            for (int j = 0; j < 2; j++) {
                wmma::load_matrix_sync(bH[j], sBh + (wn0 + 16 * j) * 40 + kk, 40);
                wmma::load_matrix_sync(bL[j], sBl + (wn0 + 16 * j) * 40 + kk, 40);
            }
#pragma unroll
            for (int i = 0; i < 2; i++)
#pragma unroll
                for (int j = 0; j < 2; j++) {
                    wmma::mma_sync(c[i][j], aH[i], bH[j], c[i][j]);
                    wmma::mma_sync(c[i][j], aH[i], bL[j], c[i][j]);
                    wmma::mma_sync(c[i][j], aL[i], bH[j], c[i][j]);
                }
        }
        __syncthreads();
    }
}

// A stored [K,M] row-major (K-major), B stored [K,N] row-major; C = A^T-view @ B
__device__ __forceinline__ void gemm_kk(
    const __nv_bfloat16* __restrict__ Ah, const __nv_bfloat16* __restrict__ Al, int lda, int m0,
    const __nv_bfloat16* __restrict__ Bh, const __nv_bfloat16* __restrict__ Bl, int ldb, int n0,
    int K, float* smem, FragC c[2][2])
{
    const int tid = threadIdx.x;
    const int wid = tid >> 5;
    const int wm0 = (wid >> 1) * 32;
    const int wn0 = (wid & 1) * 32;
    __nv_bfloat16* sAh = (__nv_bfloat16*)smem;            // [32][136]
    __nv_bfloat16* sAl = sAh + 32 * 136;
    __nv_bfloat16* sBh = sAl + 32 * 136;                  // [32][72]
    __nv_bfloat16* sBl = sBh + 32 * 72;
#pragma unroll
    for (int i = 0; i < 2; i++)
#pragma unroll
        for (int j = 0; j < 2; j++) wmma::fill_fragment(c[i][j], 0.f);

    const int rA = tid >> 3, cA = (tid & 7) * 16;
    const int rB = tid >> 3, cB = (tid & 7) * 8;
    for (int k0 = 0; k0 < K; k0 += 32) {
        const __nv_bfloat16* pAh = Ah + (size_t)(k0 + rA) * lda + m0 + cA;
        const __nv_bfloat16* pAl = Al + (size_t)(k0 + rA) * lda + m0 + cA;
        *(uint4*)(sAh + rA * 136 + cA)     = *(const uint4*)pAh;
        *(uint4*)(sAh + rA * 136 + cA + 8) = *(const uint4*)(pAh + 8);
        *(uint4*)(sAl + rA * 136 + cA)     = *(const uint4*)pAl;
        *(uint4*)(sAl + rA * 136 + cA + 8) = *(const uint4*)(pAl + 8);
        *(uint4*)(sBh + rB * 72 + cB) = *(const uint4*)(Bh + (size_t)(k0 + rB) * ldb + n0 + cB);
        *(uint4*)(sBl + rB * 72 + cB) = *(const uint4*)(Bl + (size_t)(k0 + rB) * ldb + n0 + cB);
        __syncthreads();
#pragma unroll
        for (int kk = 0; kk < 32; kk += 16) {
            wmma::fragment<wmma::matrix_a, 16, 16, 16, __nv_bfloat16, wmma::col_major> aH[2], aL[2];
            wmma::fragment<wmma::matrix_b, 16, 16, 16, __nv_bfloat16, wmma::row_major> bH[2], bL[2];
#pragma unroll
            for (int i = 0; i < 2; i++) {
                wmma::load_matrix_sync(aH[i], sAh + kk * 136 + wm0 + 16 * i, 136);
                wmma::load_matrix_sync(aL[i], sAl + kk * 136 + wm0 + 16 * i, 136);
            }
#pragma unroll
            for (int j = 0; j < 2; j++) {
                wmma::load_matrix_sync(bH[j], sBh + kk * 72 + wn0 + 16 * j, 72);
                wmma::load_matrix_sync(bL[j], sBl + kk * 72 + wn0 + 16 * j, 72);
            }
#pragma unroll
            for (int i = 0; i < 2; i++)
#pragma unroll
                for (int j = 0; j < 2; j++) {
                    wmma::mma_sync(c[i][j], aH[i], bH[j], c[i][j]);
                    wmma::mma_sync(c[i][j], aH[i], bL[j], c[i][j]);
                    wmma::mma_sync(c[i][j], aL[i], bH[j], c[i][j]);
                }
        }
        __syncthreads();
    }
}

// store accumulators to per-warp smem scratch (32x36) and return pointer
__device__ __forceinline__ float* epi_store(FragC c[2][2], float* smem, int wid)
{
    float* sC = smem + wid * (32 * 36);
#pragma unroll
    for (int i = 0; i < 2; i++)
#pragma unroll
        for (int j = 0; j < 2; j++)
            wmma::store_matrix_sync(sC + i * 16 * 36 + j * 16, c[i][j], 36, wmma::mem_row_major);
    __syncwarp();
    return sC;
}

// ---- qkv: proj_z[atom][hc] = in_z @ W_z^T + b_z, written as hi/lo bf16 ----
__global__ void __launch_bounds__(256) qkv_wmma(
    const float* __restrict__ bq, const float* __restrict__ bk, const float* __restrict__ bv)
{
    __shared__ float smem[9472];
    const int tid = threadIdx.x, wid = tid >> 5, lane = tid & 31;
    const int z  = blockIdx.z;
    const int m0 = blockIdx.y * 128;   // atom
    const int n0 = blockIdx.x * 64;    // hc
    const float* bias = (z == 0) ? bq : (z == 1) ? bk : bv;
    FragC c[2][2];
    gemm_rr(g_split_h + (size_t)z * SEG,       g_split_l + (size_t)z * SEG,       INC, m0,
            g_split_h + (size_t)(3 + z) * SEG, g_split_l + (size_t)(3 + z) * SEG, INC, n0,
            INC, smem, c);
    const int wm0 = (wid >> 1) * 32, wn0 = (wid & 1) * 32;
    float* sC = epi_store(c, smem, wid);
    const int atom = m0 + wm0 + lane;
    const size_t ob = (size_t)z * NA * HC + (size_t)atom * HC + n0 + wn0;
    union { __nv_bfloat16 b[32]; uint4 u[4]; } H, L;
#pragma unroll
    for (int col = 0; col < 32; col++) {
        float val = sC[lane * 36 + col] + bias[n0 + wn0 + col];
        split2(val, H.b[col], L.b[col]);
    }
#pragma unroll
    for (int t = 0; t < 4; t++) {
        *(uint4*)(g_ph + ob + t * 8) = H.u[t];
        *(uint4*)(g_pl + ob + t * 8) = L.u[t];
    }
}

// ---- s0: ES0[h][a][n] = exp(dot(kp_a, qp_n)/sqrt(D)) ----
__global__ void __launch_bounds__(256) s0_wmma()
{
    __shared__ float smem[9472];
    const int tid = threadIdx.x, wid = tid >> 5, lane = tid & 31;
    const int h  = blockIdx.z;
    const int m0 = blockIdx.y * 128;   // a
    const int n0 = blockIdx.x * 64;    // n
    FragC c[2][2];
    gemm_rr(g_ph + 1 * NA * HC + h * HD, g_pl + 1 * NA * HC + h * HD, HC, m0,
            g_ph + 0 * NA * HC + h * HD, g_pl + 0 * NA * HC + h * HD, HC, n0,
            HD, smem, c);
    const int wm0 = (wid >> 1) * 32, wn0 = (wid & 1) * 32;
    float* sC = epi_store(c, smem, wid);
    const int a = m0 + wm0 + lane;
    const float scale = 0.08838834764831845f;   // 1/sqrt(128)
    float* dst = g_ES0 + ((size_t)h * NA + a) * NA + n0 + wn0;
#pragma unroll
    for (int t = 0; t < 8; t++) {
        float4 r;
        r.x = __expf(sC[lane * 36 + t * 4 + 0] * scale);
        r.y = __expf(sC[lane * 36 + t * 4 + 1] * scale);
        r.z = __expf(sC[lane * 36 + t * 4 + 2] * scale);
        r.w = __expf(sC[lane * 36 + t * 4 + 3] * scale);
        *(float4*)(dst + t * 4) = r;
    }
}

// ---- out2: attn[n][h*HD+d] = sum_a W2[h][a][n] * vp[a][h*HD+d] ----
__global__ void __launch_bounds__(256) out2_wmma()
{
    __shared__ float smem[9472];
    const int tid = threadIdx.x, wid = tid >> 5, lane = tid & 31;
    const int h  = blockIdx.z;
    const int m0 = blockIdx.y * 128;   // n
    const int n0 = blockIdx.x * 64;    // d
    FragC c[2][2];
    gemm_kk(g_W2h + (size_t)h * NA * NA, g_W2l + (size_t)h * NA * NA, NA, m0,
            g_ph + 2 * NA * HC + h * HD, g_pl + 2 * NA * HC + h * HD, HC, n0,
            NA, smem, c);
    const int wm0 = (wid >> 1) * 32, wn0 = (wid & 1) * 32;
    float* sC = epi_store(c, smem, wid);
    const int n = m0 + wm0 + lane;
    float* dst = g_attn + (size_t)n * HC + h * HD + n0 + wn0;
#pragma unroll
    for (int t = 0; t < 8; t++) {
        float4 r;
        r.x = sC[lane * 36 + t * 4 + 0];
        r.y = sC[lane * 36 + t * 4 + 1];
        r.z = sC[lane * 36 + t * 4 + 2];
        r.w = sC[lane * 36 + t * 4 + 3];
        *(float4*)(dst + t * 4) = r;
    }
}

// ---- final: out[n][ic] = ln @ Wo^T + bo ----
__global__ void __launch_bounds__(256) final_wmma(
    const float* __restrict__ bo, float* __restrict__ out)
{
    __shared__ float smem[9472];
    const int tid = threadIdx.x, wid = tid >> 5, lane = tid & 31;
    const int m0 = blockIdx.y * 128;   // n
    const int n0 = blockIdx.x * 64;    // ic
    FragC c[2][2];
    gemm_rr(g_lnh, g_lnl, HC, m0,
            g_split_h + 6 * SEG, g_split_l + 6 * SEG, HC, n0,
            HC, smem, c);
    const int wm0 = (wid >> 1) * 32, wn0 = (wid & 1) * 32;
    float* sC = epi_store(c, smem, wid);
    const int n = m0 + wm0 + lane;
    float* dst = out + (size_t)n * INC + n0 + wn0;
#pragma unroll
    for (int t = 0; t < 8; t++) {
        float4 r;
        r.x = sC[lane * 36 + t * 4 + 0] + bo[n0 + wn0 + t * 4 + 0];
        r.y = sC[lane * 36 + t * 4 + 1] + bo[n0 + wn0 + t * 4 + 1];
        r.z = sC[lane * 36 + t * 4 + 2] + bo[n0 + wn0 + t * 4 + 2];
        r.w = sC[lane * 36 + t * 4 + 3] + bo[n0 + wn0 + t * 4 + 3];
        *(float4*)(dst + t * 4) = r;
    }
}

// ---------------- EB[m][n] = exp(attn_bias[n][m]) ----------------
__global__ void __launch_bounds__(256) transpose_exp(const float* __restrict__ src)
{
    __shared__ float tile[64][65];
    const int m0 = blockIdx.x * 64, n0 = blockIdx.y * 64;
    const int tid = threadIdx.x;
    const int r = tid >> 4, c4 = (tid & 15) * 4;
#pragma unroll
    for (int p = 0; p < 4; p++) {
        float4 vld = *(const float4*)(src + (size_t)(n0 + r + p * 16) * MM + m0 + c4);
        tile[r + p * 16][c4 + 0] = vld.x;
        tile[r + p * 16][c4 + 1] = vld.y;
        tile[r + p * 16][c4 + 2] = vld.z;
        tile[r + p * 16][c4 + 3] = vld.w;
    }
    __syncthreads();
#pragma unroll
    for (int p = 0; p < 4; p++) {
        const int mloc = r + p * 16;
        float4 o;
        o.x = __expf(tile[c4 + 0][mloc]);
        o.y = __expf(tile[c4 + 1][mloc]);
        o.z = __expf(tile[c4 + 2][mloc]);
        o.w = __expf(tile[c4 + 3][mloc]);
        *(float4*)(g_EB + (size_t)(m0 + mloc) * NA + n0 + c4) = o;
    }
}

// ---------------- segment boundaries ----------------
__global__ void seg_kernel(const int* __restrict__ batch_index)
{
    const int b = threadIdx.x;
    if (b <= BB) {
        int lo = 0, hi = EE;
        while (lo < hi) {
            int mid = (lo + hi) >> 1;
            if (batch_index[mid] < b) lo = mid + 1; else hi = mid;
        }
        g_seg[b] = lo;
    }
}

// ---------------- CSR build (deterministic) ----------------
__global__ void __launch_bounds__(256) deg_kernel(const int* __restrict__ atom_index)
{
    const int w = (blockIdx.x * 256 + threadIdx.x) >> 5;
    const int lane = threadIdx.x & 31;
    int cnt = 0;
    for (int base = 0; base < EE; base += 32) {
        int a = atom_index[base + lane];
        unsigned mask = __ballot_sync(0xffffffffu, a == w);
        cnt += __popc(mask);
    }
    if (lane == 0) g_deg[w] = cnt;
}

__global__ void __launch_bounds__(1024) scan_kernel()
{
    __shared__ int buf[1024];
    const int tid = threadIdx.x;
    buf[tid] = g_deg[tid];
    __syncthreads();
    for (int s = 1; s < 1024; s <<= 1) {
        int v = (tid >= s) ? buf[tid - s] : 0;
        __syncthreads();
        buf[tid] += v;
        __syncthreads();
    }
    g_off[tid + 1] = buf[tid];
    if (tid == 0) g_off[0] = 0;
}

__global__ void __launch_bounds__(256) fill_kernel(const int* __restrict__ atom_index)
{
    const int w = (blockIdx.x * 256 + threadIdx.x) >> 5;
    const int lane = threadIdx.x & 31;
    int o = g_off[w];
    for (int base = 0; base < EE; base += 32) {
        int a = atom_index[base + lane];
        bool match = (a == w);
        unsigned mask = __ballot_sync(0xffffffffu, match);
        int rank = __popc(mask & ((1u << lane) - 1));
        if (match) g_csr[o + rank] = base + lane;
        o += __popc(mask);
    }
}

// ---- C[b][h][n] = 1 / (sum_{e in b} env_e * EB[mp_e][n] * ES0[h][a_e][n] + 1e-16) ----
__global__ void __launch_bounds__(256) csum_kernel(
    const int* __restrict__ atom_index, const int* __restrict__ edge_map,
    const float* __restrict__ envelope)
{
    const int b = blockIdx.y;
    const int n = blockIdx.x * 256 + threadIdx.x;
    const int s0 = g_seg[b], s1 = g_seg[b + 1];
    __shared__ int   s_a[128], s_mp[128];
    __shared__ float s_env[128];
    float acc[NH] = {};
    for (int c = s0; c < s1; c += 128) {
        const int cnt = min(128, s1 - c);
        __syncthreads();
        if (threadIdx.x < cnt) {
            int e = c + threadIdx.x;
            int mp = edge_map[e];
            s_a[threadIdx.x]   = atom_index[e];
            s_mp[threadIdx.x]  = mp;
            s_env[threadIdx.x] = envelope[mp];
        }
        __syncthreads();
        for (int i = 0; i < cnt; i++) {
            float val = s_env[i] * g_EB[(size_t)s_mp[i] * NA + n];
            const float* es = g_ES0 + (size_t)s_a[i] * NA + n;
#pragma unroll
            for (int h = 0; h < NH; h++)
                acc[h] += val * es[(size_t)h * NA * NA];
        }
    }
#pragma unroll
    for (int h = 0; h < NH; h++)
        g_C[((size_t)b * NH + h) * NA + n] = 1.f / (acc[h] + 1e-16f);
}

// ---- W2[h][a][n] = ES0[h][a][n] * sum_{e->a} env_e^2 * EB[mp_e][n] * C[b_e][h][n] ----
// written directly as hi/lo bf16 for out2's MMA
__global__ void __launch_bounds__(128) w2_kernel(
    const int* __restrict__ edge_map, const int* __restrict__ batch_index,
    const float* __restrict__ envelope)
{
    const int a = blockIdx.y;
    const int n = blockIdx.x * 128 + threadIdx.x;
    const int o0 = g_off[a], o1 = g_off[a + 1];
    float acc[NH] = {};
    for (int j = o0; j < o1; j++) {
        int e  = g_csr[j];
        int mp = edge_map[e];
        int bb = batch_index[e];
        float env = envelope[mp];
        float t = env * env * g_EB[(size_t)mp * NA + n];
        const float* Cb = g_C + (size_t)bb * NH * NA + n;
#pragma unroll
        for (int h = 0; h < NH; h++)
            acc[h] += t * Cb[(size_t)h * NA];
    }
#pragma unroll
    for (int h = 0; h < NH; h++) {
        const size_t idx = ((size_t)h * NA + a) * NA + n;
        float val = g_ES0[idx] * acc[h];
        split2(val, g_W2h[idx], g_W2l[idx]);
    }
}

// ---------------- LayerNorm -> hi/lo bf16 ----------------
__global__ void __launch_bounds__(256) ln_kernel(
    const float* __restrict__ ln_g, const float* __restrict__ ln_b)
{
    const int n = blockIdx.x;
    const int tid = threadIdx.x;
    const float* x = g_attn + (size_t)n * HC;
    float s = 0.f, s2 = 0.f;
    for (int i = tid; i < HC; i += 256) {
        float v = x[i];
        s += v; s2 += v * v;
    }
#pragma unroll
    for (int o = 16; o > 0; o >>= 1) {
        s  += __shfl_xor_sync(0xffffffffu, s, o);
        s2 += __shfl_xor_sync(0xffffffffu, s2, o);
    }
    __shared__ float ws[8], ws2[8], stats[2];
    if ((tid & 31) == 0) { ws[tid >> 5] = s; ws2[tid >> 5] = s2; }
    __syncthreads();
    if (tid == 0) {
        float a = 0.f, b = 0.f;
#pragma unroll
        for (int i = 0; i < 8; i++) { a += ws[i]; b += ws2[i]; }
        float mean = a * (1.f / HC);
        float var  = b * (1.f / HC) - mean * mean;
        stats[0] = mean;
        stats[1] = rsqrtf(var + 1e-7f);
    }
    __syncthreads();
    const float mean = stats[0], inv = stats[1];
    for (int i = tid; i < HC; i += 256) {
        float val = (x[i] - mean) * inv * ln_g[i] + ln_b[i];
        split2(val, g_lnh[(size_t)n * HC + i], g_lnl[(size_t)n * HC + i]);
    }
}

// ---------------- launch ----------------
extern "C" void kernel_launch(void* const* d_in, const int* in_sizes, int n_in,
                              void* d_out, int out_size)
{
    const float* q         = (const float*)d_in[0];
    const float* k         = (const float*)d_in[1];
    const float* v         = (const float*)d_in[2];
    const float* envelope  = (const float*)d_in[3];
    const float* attn_bias = (const float*)d_in[4];
    const float* Wq        = (const float*)d_in[5];
    const float* bq        = (const float*)d_in[6];
    const float* Wk        = (const float*)d_in[7];
    const float* bk        = (const float*)d_in[8];
    const float* Wv        = (const float*)d_in[9];
    const float* bv        = (const float*)d_in[10];
    const float* ln_g      = (const float*)d_in[11];
    const float* ln_b      = (const float*)d_in[12];
    const float* Wo        = (const float*)d_in[13];
    const float* bo        = (const float*)d_in[14];
    const int* atom_index  = (const int*)d_in[15];
    const int* batch_index = (const int*)d_in[16];
    const int* edge_map    = (const int*)d_in[17];
    float* out = (float*)d_out;

    // split all external GEMM operands into hi/lo bf16
    split_kernel<<<dim3(SEG / 1024, 7), 256>>>(q, k, v, Wq, Wk, Wv, Wo);

    transpose_exp<<<dim3(MM / 64, NA / 64), 256>>>(attn_bias);
    seg_kernel<<<1, 128>>>(batch_index);
    deg_kernel<<<NA / 8, 256>>>(atom_index);
    scan_kernel<<<1, 1024>>>();
    fill_kernel<<<NA / 8, 256>>>(atom_index);

    // projections (tensor cores, split-bf16), writes hi/lo directly
    qkv_wmma<<<dim3(HC / 64, NA / 128, 3), 256>>>(bq, bk, bv);

    // dense per-atom exp(scores)
    s0_wmma<<<dim3(NA / 64, NA / 128, NH), 256>>>();

    // softmax denominators + per-atom weights (weights written as hi/lo bf16)
    csum_kernel<<<dim3(NA / 256, BB), 256>>>(atom_index, edge_map, envelope);
    w2_kernel<<<dim3(NA / 128, NA), 128>>>(edge_map, batch_index, envelope);

    // attention output (tensor cores)
    out2_wmma<<<dim3(HD / 64, NA / 128, NH), 256>>>();

    ln_kernel<<<NA, 256>>>(ln_g, ln_b);

    // final projection (tensor cores)
    final_wmma<<<dim3(INC / 64, NA / 128), 256>>>(bo, out);
}

// round 10
// speedup vs baseline: 5.0004x; 1.0368x over previous
#include <cuda_runtime.h>
#include <cuda_bf16.h>
#include <mma.h>
#include <cstdint>
#include <math.h>

using namespace nvcuda;

// Problem constants
#define NA  1024   // N atoms
#define EE  8192   // E edges
#define MM  8192   // M envelope table
#define BB  64     // B batches
#define INC 512    // IN_CH
#define HC  1024   // H_CH
#define NH  8      // heads
#define HD  128    // head dim

#define SEG 524288 // elements per split slab (all 7 external operands are 512K elems)

// ---------------- scratch ----------------
__device__ __nv_bfloat16 g_split_h[7 * SEG];     // q,k,v,Wq,Wk,Wv,Wo (hi)
__device__ __nv_bfloat16 g_split_l[7 * SEG];     // (lo)
__device__ __nv_bfloat16 g_ph[3 * NA * HC];      // qp/kp/vp hi
__device__ __nv_bfloat16 g_pl[3 * NA * HC];      // qp/kp/vp lo
__device__ __nv_bfloat16 g_lnh[NA * HC];
__device__ __nv_bfloat16 g_lnl[NA * HC];
__device__ __nv_bfloat16 g_W2h[(size_t)NH * NA * NA];
__device__ __nv_bfloat16 g_W2l[(size_t)NH * NA * NA];
__device__ float g_EB[(size_t)MM * NA];          // exp(attn_bias^T)[m][n]
__device__ float g_ES0[(size_t)NH * NA * NA];    // exp(S0)[h][a][n]
__device__ float g_C[BB * NH * NA];
__device__ float g_attn[NA * HC];
__device__ int   g_seg[BB + 1];
__device__ int   g_off[NA + 1];
__device__ int   g_csr[EE];

__device__ __forceinline__ void split2(float v, __nv_bfloat16& h, __nv_bfloat16& l) {
    h = __float2bfloat16(v);
    l = __float2bfloat16(v - __bfloat162float(h));
}

__device__ __forceinline__ uint32_t smem_u32(const void* p) {
    return (uint32_t)__cvta_generic_to_shared(p);
}
__device__ __forceinline__ void cp16(uint32_t dst, const void* src) {
    asm volatile("cp.async.cg.shared.global [%0], [%1], 16;" :: "r"(dst), "l"(src));
}
#define CP_COMMIT asm volatile("cp.async.commit_group;" ::: "memory")

// ---------------- split the 7 external fp32 operands into hi/lo bf16 ----------------
__global__ void __launch_bounds__(256) split_kernel(
    const float* __restrict__ q,  const float* __restrict__ k,  const float* __restrict__ v,
    const float* __restrict__ Wq, const float* __restrict__ Wk, const float* __restrict__ Wv,
    const float* __restrict__ Wo)
{
    const float* srcs[7] = {q, k, v, Wq, Wk, Wv, Wo};
    const float* s = srcs[blockIdx.y];
    const size_t base = (size_t)blockIdx.y * SEG;
    const int i0 = (blockIdx.x * 256 + threadIdx.x) * 4;
    float4 f = *(const float4*)(s + i0);
    union { __nv_bfloat16 b[4]; uint2 u; } H, L;
    split2(f.x, H.b[0], L.b[0]);
    split2(f.y, H.b[1], L.b[1]);
    split2(f.z, H.b[2], L.b[2]);
    split2(f.w, H.b[3], L.b[3]);
    *(uint2*)(g_split_h + base + i0) = H.u;
    *(uint2*)(g_split_l + base + i0) = L.u;
}

// ================= pipelined wmma GEMM cores =================
// Split bf16: C += Ah@Bh^T + Ah@Bl^T + Al@Bh^T  (fp32 accum), K chunk 32, 2 stages.
typedef wmma::fragment<wmma::accumulator, 16, 16, 16, float> FragC;

// ---- rr: A [M,K] row-major (M tile 128), B [N,K] row-major (N tile NT) ----
// smem stage layout: Ah [128][40], Al [128][40], Bh [NT][40], Bl [NT][40]
template<int NT>
__device__ __forceinline__ void rr_load(
    const __nv_bfloat16* __restrict__ Ah, const __nv_bfloat16* __restrict__ Al, int lda, int m0,
    const __nv_bfloat16* __restrict__ Bh, const __nv_bfloat16* __restrict__ Bl, int ldb, int n0,
    int k0, uint32_t stage)
{
    const int tid = threadIdx.x;
#pragma unroll
    for (int rep = 0; rep < 2; rep++) {
        int idx = tid + rep * 256;             // 512 chunks: 128 rows x 4
        int r = idx >> 2, c8 = (idx & 3) * 8;
        uint32_t d = stage + (uint32_t)(r * 40 + c8) * 2;
        size_t off = (size_t)(m0 + r) * lda + k0 + c8;
        cp16(d, Ah + off);
        cp16(d + 10240, Al + off);
    }
#pragma unroll
    for (int rep = 0; rep < NT / 64; rep++) {
        int idx = tid + rep * 256;
        int r = idx >> 2, c8 = (idx & 3) * 8;
        uint32_t d = stage + 20480 + (uint32_t)(r * 40 + c8) * 2;
        size_t off = (size_t)(n0 + r) * ldb + k0 + c8;
        cp16(d, Bh + off);
        cp16(d + NT * 80, Bl + off);
    }
}

template<int NT>
__device__ __forceinline__ void rr_compute(const char* st, FragC (&c)[2][NT / 32])
{
    const int wid = threadIdx.x >> 5;
    const int wm0 = (wid >> 1) * 32;
    const int wn0 = (wid & 1) * (NT / 2);
    const __nv_bfloat16* sAh = (const __nv_bfloat16*)st;
    const __nv_bfloat16* sAl = sAh + 128 * 40;
    const __nv_bfloat16* sBh = (const __nv_bfloat16*)(st + 20480);
    const __nv_bfloat16* sBl = sBh + NT * 40;
    constexpr int FN = NT / 32;
#pragma unroll
    for (int kk = 0; kk < 32; kk += 16) {
        wmma::fragment<wmma::matrix_a, 16, 16, 16, __nv_bfloat16, wmma::row_major> aH[2], aL[2];
        wmma::fragment<wmma::matrix_b, 16, 16, 16, __nv_bfloat16, wmma::col_major> bH[FN], bL[FN];
#pragma unroll
        for (int i = 0; i < 2; i++) {
            wmma::load_matrix_sync(aH[i], sAh + (wm0 + 16 * i) * 40 + kk, 40);
            wmma::load_matrix_sync(aL[i], sAl + (wm0 + 16 * i) * 40 + kk, 40);
        }
#pragma unroll
        for (int j = 0; j < FN; j++) {
            wmma::load_matrix_sync(bH[j], sBh + (wn0 + 16 * j) * 40 + kk, 40);
            wmma::load_matrix_sync(bL[j], sBl + (wn0 + 16 * j) * 40 + kk, 40);
        }
#pragma unroll
        for (int i = 0; i < 2; i++)
#pragma unroll
            for (int j = 0; j < FN; j++) {
                wmma::mma_sync(c[i][j], aH[i], bH[j], c[i][j]);
                wmma::mma_sync(c[i][j], aH[i], bL[j], c[i][j]);
                wmma::mma_sync(c[i][j], aL[i], bH[j], c[i][j]);
            }
    }
}

template<int NT>
__device__ __forceinline__ void gemm_rr_pipe(
    const __nv_bfloat16* Ah, const __nv_bfloat16* Al, int lda, int m0,
    const __nv_bfloat16* Bh, const __nv_bfloat16* Bl, int ldb, int n0,
    int K, char* smem, FragC (&c)[2][NT / 32])
{
    const int SSTR = 20480 + NT * 160;
    uint32_t sb = smem_u32(smem);
#pragma unroll
    for (int i = 0; i < 2; i++)
#pragma unroll
        for (int j = 0; j < NT / 32; j++) wmma::fill_fragment(c[i][j], 0.f);
    rr_load<NT>(Ah, Al, lda, m0, Bh, Bl, ldb, n0, 0, sb);
    CP_COMMIT;
    const int NC = K / 32;
    for (int ch = 0; ch < NC; ch++) {
        if (ch + 1 < NC) {
            rr_load<NT>(Ah, Al, lda, m0, Bh, Bl, ldb, n0, (ch + 1) * 32,
                        sb + ((ch + 1) & 1) * SSTR);
            CP_COMMIT;
            asm volatile("cp.async.wait_group 1;" ::: "memory");
        } else {
            asm volatile("cp.async.wait_group 0;" ::: "memory");
        }
        __syncthreads();
        rr_compute<NT>(smem + (ch & 1) * SSTR, c);
        __syncthreads();
    }
}

// ---- kk: A [K,M] K-major (M tile 128), B [K,N] K-major (N tile 64) ----
// smem stage: Ah [32][136], Al [32][136], Bh [32][72], Bl [32][72]; stride 26624
__device__ __forceinline__ void kk_load(
    const __nv_bfloat16* __restrict__ Ah, const __nv_bfloat16* __restrict__ Al, int lda, int m0,
    const __nv_bfloat16* __restrict__ Bh, const __nv_bfloat16* __restrict__ Bl, int ldb, int n0,
    int k0, uint32_t stage)
{
    const int tid = threadIdx.x;
#pragma unroll
    for (int rep = 0; rep < 2; rep++) {
        int idx = tid + rep * 256;              // 512 chunks: 32 rows x 16
        int r = idx >> 4, c8 = (idx & 15) * 8;
        uint32_t d = stage + (uint32_t)(r * 136 + c8) * 2;
        size_t off = (size_t)(k0 + r) * lda + m0 + c8;
        cp16(d, Ah + off);
        cp16(d + 8704, Al + off);
    }
    {
        int r = tid >> 3, c8 = (tid & 7) * 8;   // 256 chunks: 32 rows x 8
        uint32_t d = stage + 17408 + (uint32_t)(r * 72 + c8) * 2;
        size_t off = (size_t)(k0 + r) * ldb + n0 + c8;
        cp16(d, Bh + off);
        cp16(d + 4608, Bl + off);
    }
}

__device__ __forceinline__ void kk_compute(const char* st, FragC (&c)[2][2])
{
    const int wid = threadIdx.x >> 5;
    const int wm0 = (wid >> 1) * 32;
    const int wn0 = (wid & 1) * 32;
    const __nv_bfloat16* sAh = (const __nv_bfloat16*)st;
    const __nv_bfloat16* sAl = sAh + 32 * 136;
    const __nv_bfloat16* sBh = (const __nv_bfloat16*)(st + 17408);
    const __nv_bfloat16* sBl = sBh + 32 * 72;
#pragma unroll
    for (int kk = 0; kk < 32; kk += 16) {
        wmma::fragment<wmma::matrix_a, 16, 16, 16, __nv_bfloat16, wmma::col_major> aH[2], aL[2];
        wmma::fragment<wmma::matrix_b, 16, 16, 16, __nv_bfloat16, wmma::row_major> bH[2], bL[2];
#pragma unroll
        for (int i = 0; i < 2; i++) {
            wmma::load_matrix_sync(aH[i], sAh + kk * 136 + wm0 + 16 * i, 136);
            wmma::load_matrix_sync(aL[i], sAl + kk * 136 + wm0 + 16 * i, 136);
        }
#pragma unroll
        for (int j = 0; j < 2; j++) {
            wmma::load_matrix_sync(bH[j], sBh + kk * 72 + wn0 + 16 * j, 72);
            wmma::load_matrix_sync(bL[j], sBl + kk * 72 + wn0 + 16 * j, 72);
        }
#pragma unroll
        for (int i = 0; i < 2; i++)
#pragma unroll
            for (int j = 0; j < 2; j++) {
                wmma::mma_sync(c[i][j], aH[i], bH[j], c[i][j]);
                wmma::mma_sync(c[i][j], aH[i], bL[j], c[i][j]);
                wmma::mma_sync(c[i][j], aL[i], bH[j], c[i][j]);
            }
    }
}

__device__ __forceinline__ void gemm_kk_pipe(
    const __nv_bfloat16* Ah, const __nv_bfloat16* Al, int lda, int m0,
    const __nv_bfloat16* Bh, const __nv_bfloat16* Bl, int ldb, int n0,
    int K, char* smem, FragC (&c)[2][2])
{
    const int SSTR = 26624;
    uint32_t sb = smem_u32(smem);
#pragma unroll
    for (int i = 0; i < 2; i++)
#pragma unroll
        for (int j = 0; j < 2; j++) wmma::fill_fragment(c[i][j], 0.f);
    kk_load(Ah, Al, lda, m0, Bh, Bl, ldb, n0, 0, sb);
    CP_COMMIT;
    const int NC = K / 32;
    for (int ch = 0; ch < NC; ch++) {
        if (ch + 1 < NC) {
            kk_load(Ah, Al, lda, m0, Bh, Bl, ldb, n0, (ch + 1) * 32,
                    sb + ((ch + 1) & 1) * SSTR);
            CP_COMMIT;
            asm volatile("cp.async.wait_group 1;" ::: "memory");
        } else {
            asm volatile("cp.async.wait_group 0;" ::: "memory");
        }
        __syncthreads();
        kk_compute(smem + (ch & 1) * SSTR, c);
        __syncthreads();
    }
}

// epilogue scratch overlay: per warp 32 x (WN+4) floats on top of pipeline smem
template<int WN, int FN>
__device__ __forceinline__ float* epi_store(FragC (&c)[2][FN], char* smem, int wid)
{
    float* sC = (float*)smem + wid * 32 * (WN + 4);
#pragma unroll
    for (int i = 0; i < 2; i++)
#pragma unroll
        for (int j = 0; j < FN; j++)
            wmma::store_matrix_sync(sC + i * 16 * (WN + 4) + j * 16, c[i][j],
                                    WN + 4, wmma::mem_row_major);
    __syncwarp();
    return sC;
}

// ---- qkv: proj_z[atom][hc] = in_z @ W_z^T + b_z, written as hi/lo bf16 ----
__global__ void __launch_bounds__(256) qkv_wmma(
    const float* __restrict__ bq, const float* __restrict__ bk, const float* __restrict__ bv)
{
    extern __shared__ char smem[];
    const int tid = threadIdx.x, wid = tid >> 5, lane = tid & 31;
    const int z  = blockIdx.z;
    const int m0 = blockIdx.y * 128;   // atom
    const int n0 = blockIdx.x * 128;   // hc
    const float* bias = (z == 0) ? bq : (z == 1) ? bk : bv;
    FragC c[2][4];
    gemm_rr_pipe<128>(g_split_h + (size_t)z * SEG,       g_split_l + (size_t)z * SEG,       INC, m0,
                      g_split_h + (size_t)(3 + z) * SEG, g_split_l + (size_t)(3 + z) * SEG, INC, n0,
                      INC, smem, c);
    float* sC = epi_store<64, 4>(c, smem, wid);
    const int wm0 = (wid >> 1) * 32, wn0 = (wid & 1) * 64;
    const int atom = m0 + wm0 + lane;
    const size_t ob = (size_t)z * NA * HC + (size_t)atom * HC + n0 + wn0;
    union { __nv_bfloat16 b[8]; uint4 u; } H, L;
#pragma unroll
    for (int t = 0; t < 8; t++) {
#pragma unroll
        for (int e = 0; e < 8; e++) {
            float val = sC[lane * 68 + t * 8 + e] + bias[n0 + wn0 + t * 8 + e];
            split2(val, H.b[e], L.b[e]);
        }
        *(uint4*)(g_ph + ob + t * 8) = H.u;
        *(uint4*)(g_pl + ob + t * 8) = L.u;
    }
}

// ---- s0: ES0[h][a][n] = exp(dot(kp_a, qp_n)/sqrt(D)) ----
__global__ void __launch_bounds__(256) s0_wmma()
{
    extern __shared__ char smem[];
    const int tid = threadIdx.x, wid = tid >> 5, lane = tid & 31;
    const int h  = blockIdx.z;
    const int m0 = blockIdx.y * 128;   // a
    const int n0 = blockIdx.x * 128;   // n
    FragC c[2][4];
    gemm_rr_pipe<128>(g_ph + 1 * NA * HC + h * HD, g_pl + 1 * NA * HC + h * HD, HC, m0,
                      g_ph + 0 * NA * HC + h * HD, g_pl + 0 * NA * HC + h * HD, HC, n0,
                      HD, smem, c);
    float* sC = epi_store<64, 4>(c, smem, wid);
    const int wm0 = (wid >> 1) * 32, wn0 = (wid & 1) * 64;
    const int a = m0 + wm0 + lane;
    const float scale = 0.08838834764831845f;   // 1/sqrt(128)
    float* dst = g_ES0 + ((size_t)h * NA + a) * NA + n0 + wn0;
#pragma unroll
    for (int t = 0; t < 16; t++) {
        float4 r;
        r.x = __expf(sC[lane * 68 + t * 4 + 0] * scale);
        r.y = __expf(sC[lane * 68 + t * 4 + 1] * scale);
        r.z = __expf(sC[lane * 68 + t * 4 + 2] * scale);
        r.w = __expf(sC[lane * 68 + t * 4 + 3] * scale);
        *(float4*)(dst + t * 4) = r;
    }
}

// ---- out2: attn[n][h*HD+d] = sum_a W2[h][a][n] * vp[a][h*HD+d] ----
__global__ void __launch_bounds__(256) out2_wmma()
{
    extern __shared__ char smem[];
    const int tid = threadIdx.x, wid = tid >> 5, lane = tid & 31;
    const int h  = blockIdx.z;
    const int m0 = blockIdx.y * 128;   // n
    const int n0 = blockIdx.x * 64;    // d
    FragC c[2][2];
    gemm_kk_pipe(g_W2h + (size_t)h * NA * NA, g_W2l + (size_t)h * NA * NA, NA, m0,
                 g_ph + 2 * NA * HC + h * HD, g_pl + 2 * NA * HC + h * HD, HC, n0,
                 NA, smem, c);
    float* sC = epi_store<32, 2>(c, smem, wid);
    const int wm0 = (wid >> 1) * 32, wn0 = (wid & 1) * 32;
    const int n = m0 + wm0 + lane;
    float* dst = g_attn + (size_t)n * HC + h * HD + n0 + wn0;
#pragma unroll
    for (int t = 0; t < 8; t++) {
        float4 r;
        r.x = sC[lane * 36 + t * 4 + 0];
        r.y = sC[lane * 36 + t * 4 + 1];
        r.z = sC[lane * 36 + t * 4 + 2];
        r.w = sC[lane * 36 + t * 4 + 3];
        *(float4*)(dst + t * 4) = r;
    }
}

// ---- final: out[n][ic] = ln @ Wo^T + bo ----
__global__ void __launch_bounds__(256) final_wmma(
    const float* __restrict__ bo, float* __restrict__ out)
{
    extern __shared__ char smem[];
    const int tid = threadIdx.x, wid = tid >> 5, lane = tid & 31;
    const int m0 = blockIdx.y * 128;   // n
    const int n0 = blockIdx.x * 128;   // ic
    FragC c[2][4];
    gemm_rr_pipe<128>(g_lnh, g_lnl, HC, m0,
                      g_split_h + 6 * SEG, g_split_l + 6 * SEG, HC, n0,
                      HC, smem, c);
    float* sC = epi_store<64, 4>(c, smem, wid);
    const int wm0 = (wid >> 1) * 32, wn0 = (wid & 1) * 64;
    const int n = m0 + wm0 + lane;
    float* dst = out + (size_t)n * INC + n0 + wn0;
#pragma unroll
    for (int t = 0; t < 16; t++) {
        float4 r;
        r.x = sC[lane * 68 + t * 4 + 0] + bo[n0 + wn0 + t * 4 + 0];
        r.y = sC[lane * 68 + t * 4 + 1] + bo[n0 + wn0 + t * 4 + 1];
        r.z = sC[lane * 68 + t * 4 + 2] + bo[n0 + wn0 + t * 4 + 2];
        r.w = sC[lane * 68 + t * 4 + 3] + bo[n0 + wn0 + t * 4 + 3];
        *(float4*)(dst + t * 4) = r;
    }
}

// ---------------- EB[m][n] = exp(attn_bias[n][m]) ----------------
__global__ void __launch_bounds__(256) transpose_exp(const float* __restrict__ src)
{
    __shared__ float tile[64][65];
    const int m0 = blockIdx.x * 64, n0 = blockIdx.y * 64;
    const int tid = threadIdx.x;
    const int r = tid >> 4, c4 = (tid & 15) * 4;
#pragma unroll
    for (int p = 0; p < 4; p++) {
        float4 vld = *(const float4*)(src + (size_t)(n0 + r + p * 16) * MM + m0 + c4);
        tile[r + p * 16][c4 + 0] = vld.x;
        tile[r + p * 16][c4 + 1] = vld.y;
        tile[r + p * 16][c4 + 2] = vld.z;
        tile[r + p * 16][c4 + 3] = vld.w;
    }
    __syncthreads();
#pragma unroll
    for (int p = 0; p < 4; p++) {
        const int mloc = r + p * 16;
        float4 o;
        o.x = __expf(tile[c4 + 0][mloc]);
        o.y = __expf(tile[c4 + 1][mloc]);
        o.z = __expf(tile[c4 + 2][mloc]);
        o.w = __expf(tile[c4 + 3][mloc]);
        *(float4*)(g_EB + (size_t)(m0 + mloc) * NA + n0 + c4) = o;
    }
}

// ---------------- segment boundaries ----------------
__global__ void seg_kernel(const int* __restrict__ batch_index)
{
    const int b = threadIdx.x;
    if (b <= BB) {
        int lo = 0, hi = EE;
        while (lo < hi) {
            int mid = (lo + hi) >> 1;
            if (batch_index[mid] < b) lo = mid + 1; else hi = mid;
        }
        g_seg[b] = lo;
    }
}

// ---------------- CSR: histogram + scan in one CTA (atomic counting is deterministic) ----
__global__ void __launch_bounds__(1024) hist_scan_kernel(const int* __restrict__ atom_index)
{
    __shared__ int buf[1024];
    const int tid = threadIdx.x;
    buf[tid] = 0;
    __syncthreads();
#pragma unroll
    for (int i = 0; i < EE / 1024; i++)
        atomicAdd(&buf[atom_index[tid + i * 1024]], 1);
    __syncthreads();
    for (int s = 1; s < 1024; s <<= 1) {
        int v = (tid >= s) ? buf[tid - s] : 0;
        __syncthreads();
        buf[tid] += v;
        __syncthreads();
    }
    g_off[tid + 1] = buf[tid];
    if (tid == 0) g_off[0] = 0;
}

__global__ void __launch_bounds__(256) fill_kernel(const int* __restrict__ atom_index)
{
    const int w = (blockIdx.x * 256 + threadIdx.x) >> 5;
    const int lane = threadIdx.x & 31;
    int o = g_off[w];
    for (int base = 0; base < EE; base += 32) {
        int a = atom_index[base + lane];
        bool match = (a == w);
        unsigned mask = __ballot_sync(0xffffffffu, match);
        int rank = __popc(mask & ((1u << lane) - 1));
        if (match) g_csr[o + rank] = base + lane;
        o += __popc(mask);
    }
}

// ---- C[b][h][n] = 1 / (sum_{e in b} env_e * EB[mp_e][n] * ES0[h][a_e][n] + 1e-16) ----
__global__ void __launch_bounds__(256) csum_kernel(
    const int* __restrict__ atom_index, const int* __restrict__ edge_map,
    const float* __restrict__ envelope)
{
    const int b = blockIdx.y;
    const int n = blockIdx.x * 256 + threadIdx.x;
    const int s0 = g_seg[b], s1 = g_seg[b + 1];
    __shared__ int   s_a[128], s_mp[128];
    __shared__ float s_env[128];
    float acc[NH] = {};
    for (int c = s0; c < s1; c += 128) {
        const int cnt = min(128, s1 - c);
        __syncthreads();
        if (threadIdx.x < cnt) {
            int e = c + threadIdx.x;
            int mp = edge_map[e];
            s_a[threadIdx.x]   = atom_index[e];
            s_mp[threadIdx.x]  = mp;
            s_env[threadIdx.x] = envelope[mp];
        }
        __syncthreads();
        for (int i = 0; i < cnt; i++) {
            float val = s_env[i] * g_EB[(size_t)s_mp[i] * NA + n];
            const float* es = g_ES0 + (size_t)s_a[i] * NA + n;
#pragma unroll
            for (int h = 0; h < NH; h++)
                acc[h] += val * es[(size_t)h * NA * NA];
        }
    }
#pragma unroll
    for (int h = 0; h < NH; h++)
        g_C[((size_t)b * NH + h) * NA + n] = 1.f / (acc[h] + 1e-16f);
}

// ---- W2[h][a][n] = ES0[h][a][n] * sum_{e->a} env_e^2 * EB[mp_e][n] * C[b_e][h][n] ----
__global__ void __launch_bounds__(128) w2_kernel(
    const int* __restrict__ edge_map, const int* __restrict__ batch_index,
    const float* __restrict__ envelope)
{
    const int a = blockIdx.y;
    const int n = blockIdx.x * 128 + threadIdx.x;
    const int o0 = g_off[a], o1 = g_off[a + 1];
    float acc[NH] = {};
    for (int j = o0; j < o1; j++) {
        int e  = g_csr[j];
        int mp = edge_map[e];
        int bb = batch_index[e];
        float env = envelope[mp];
        float t = env * env * g_EB[(size_t)mp * NA + n];
        const float* Cb = g_C + (size_t)bb * NH * NA + n;
#pragma unroll
        for (int h = 0; h < NH; h++)
            acc[h] += t * Cb[(size_t)h * NA];
    }
#pragma unroll
    for (int h = 0; h < NH; h++) {
        const size_t idx = ((size_t)h * NA + a) * NA + n;
        float val = g_ES0[idx] * acc[h];
        split2(val, g_W2h[idx], g_W2l[idx]);
    }
}

// ---------------- LayerNorm -> hi/lo bf16 ----------------
__global__ void __launch_bounds__(256) ln_kernel(
    const float* __restrict__ ln_g, const float* __restrict__ ln_b)
{
    const int n = blockIdx.x;
    const int tid = threadIdx.x;
    const float* x = g_attn + (size_t)n * HC;
    float s = 0.f, s2 = 0.f;
    for (int i = tid; i < HC; i += 256) {
        float v = x[i];
        s += v; s2 += v * v;
    }
#pragma unroll
    for (int o = 16; o > 0; o >>= 1) {
        s  += __shfl_xor_sync(0xffffffffu, s, o);
        s2 += __shfl_xor_sync(0xffffffffu, s2, o);
    }
    __shared__ float ws[8], ws2[8], stats[2];
    if ((tid & 31) == 0) { ws[tid >> 5] = s; ws2[tid >> 5] = s2; }
    __syncthreads();
    if (tid == 0) {
        float a = 0.f, b = 0.f;
#pragma unroll
        for (int i = 0; i < 8; i++) { a += ws[i]; b += ws2[i]; }
        float mean = a * (1.f / HC);
        float var  = b * (1.f / HC) - mean * mean;
        stats[0] = mean;
        stats[1] = rsqrtf(var + 1e-7f);
    }
    __syncthreads();
    const float mean = stats[0], inv = stats[1];
    for (int i = tid; i < HC; i += 256) {
        float val = (x[i] - mean) * inv * ln_g[i] + ln_b[i];
        split2(val, g_lnh[(size_t)n * HC + i], g_lnl[(size_t)n * HC + i]);
    }
}

// ---------------- launch ----------------
extern "C" void kernel_launch(void* const* d_in, const int* in_sizes, int n_in,
                              void* d_out, int out_size)
{
    const float* q         = (const float*)d_in[0];
    const float* k         = (const float*)d_in[1];
    const float* v         = (const float*)d_in[2];
    const float* envelope  = (const float*)d_in[3];
    const float* attn_bias = (const float*)d_in[4];
    const float* Wq        = (const float*)d_in[5];
    const float* bq        = (const float*)d_in[6];
    const float* Wk        = (const float*)d_in[7];
    const float* bk        = (const float*)d_in[8];
    const float* Wv        = (const float*)d_in[9];
    const float* bv        = (const float*)d_in[10];
    const float* ln_g      = (const float*)d_in[11];
    const float* ln_b      = (const float*)d_in[12];
    const float* Wo        = (const float*)d_in[13];
    const float* bo        = (const float*)d_in[14];
    const int* atom_index  = (const int*)d_in[15];
    const int* batch_index = (const int*)d_in[16];
    const int* edge_map    = (const int*)d_in[17];
    float* out = (float*)d_out;

    const int SMEM_RR = 2 * (20480 + 128 * 160);   // 81920
    const int SMEM_KK = 2 * 26624;                 // 53248
    cudaFuncSetAttribute(qkv_wmma,   cudaFuncAttributeMaxDynamicSharedMemorySize, SMEM_RR);
    cudaFuncSetAttribute(s0_wmma,    cudaFuncAttributeMaxDynamicSharedMemorySize, SMEM_RR);
    cudaFuncSetAttribute(final_wmma, cudaFuncAttributeMaxDynamicSharedMemorySize, SMEM_RR);
    cudaFuncSetAttribute(out2_wmma,  cudaFuncAttributeMaxDynamicSharedMemorySize, SMEM_KK);

    // split all external GEMM operands into hi/lo bf16
    split_kernel<<<dim3(SEG / 1024, 7), 256>>>(q, k, v, Wq, Wk, Wv, Wo);

    transpose_exp<<<dim3(MM / 64, NA / 64), 256>>>(attn_bias);
    seg_kernel<<<1, 128>>>(batch_index);
    hist_scan_kernel<<<1, 1024>>>(atom_index);
    fill_kernel<<<NA / 8, 256>>>(atom_index);

    // projections (tensor cores, split-bf16), writes hi/lo directly
    qkv_wmma<<<dim3(HC / 128, NA / 128, 3), 256, SMEM_RR>>>(bq, bk, bv);

    // dense per-atom exp(scores)
    s0_wmma<<<dim3(NA / 128, NA / 128, NH), 256, SMEM_RR>>>();

    // softmax denominators + per-atom weights (weights written as hi/lo bf16)
    csum_kernel<<<dim3(NA / 256, BB), 256>>>(atom_index, edge_map, envelope);
    w2_kernel<<<dim3(NA / 128, NA), 128>>>(edge_map, batch_index, envelope);

    // attention output (tensor cores)
    out2_wmma<<<dim3(HD / 64, NA / 128, NH), 256, SMEM_KK>>>();

    ln_kernel<<<NA, 256>>>(ln_g, ln_b);

    // final projection (tensor cores)
    final_wmma<<<dim3(INC / 128, NA / 128), 256, SMEM_RR>>>(bo, out);
}